// round 11
// baseline (speedup 1.0000x reference)
#include <cuda_runtime.h>
#include <math.h>

// ForestRuthIntegrator v5 — K-space trajectory + packed f32x2 FFMA.
// Prologue: h0=v@U, fU=f@U via U^T d-pair packing (FFMA2).
// Evals: h' = h + ddt*(-(h*h)@WU + fU) with dup-packed h^2 (FFMA2, bitwise==v4).
// Epilogue: Gv=Sv@W, Gx=Sx@W row-pair packed (FFMA2, bitwise==v4), split v/x
// passes to halve accumulator pressure. No sv staging (gv read direct).

#define THREADS 512
#define CTA_M   32
#define DDIM    512
#define KDIM    64
#define WUS     68      // WU row stride
#define H2DS    132     // duplicated-h^2 row stride (32 rows x 128 data)
#define STS_    36      // transposed-S stride
#define UTS     132     // U^T chunk row stride (64 k x 128 d data)
#define STAGE_N 8448    // stage slot floats (fits UT 64x132 and W 64x128)

typedef unsigned long long ull;

__device__ float g_WU[KDIM * KDIM];
__device__ float g_UT[KDIM * DDIM];

__global__ void wu_kernel(const float* __restrict__ gW, const float* __restrict__ gU) {
    int idx = blockIdx.x * blockDim.x + threadIdx.x;   // 4096
    int a = idx >> 6, b = idx & 63;
    float s = 0.f;
    #pragma unroll 8
    for (int d = 0; d < DDIM; ++d)
        s = fmaf(gW[a * DDIM + d], gU[d * KDIM + b], s);
    g_WU[a * KDIM + b] = s;
}

__global__ void ut_kernel(const float* __restrict__ gU) {
    int idx = blockIdx.x * blockDim.x + threadIdx.x;   // 32768
    int k = idx >> 9, d = idx & 511;
    g_UT[k * DDIM + d] = gU[d * KDIM + k];
}

__device__ __forceinline__ void fma2(ull& d, ull a, ull b) {
    asm("fma.rn.f32x2 %0, %1, %2, %3;" : "=l"(d) : "l"(a), "l"(b), "l"(d));
}
__device__ __forceinline__ ull add2(ull a, ull b) {
    ull r; asm("add.rn.f32x2 %0, %1, %2;" : "=l"(r) : "l"(a), "l"(b)); return r;
}
__device__ __forceinline__ ull packdup(float f) {
    ull r; unsigned u = __float_as_uint(f);
    asm("mov.b64 %0, {%1, %1};" : "=l"(r) : "r"(u)); return r;
}
__device__ __forceinline__ float2 unpack2(ull v) {
    unsigned lo, hi;
    asm("mov.b64 {%0, %1}, %2;" : "=r"(lo), "=r"(hi) : "l"(v));
    return make_float2(__uint_as_float(lo), __uint_as_float(hi));
}

__device__ __forceinline__ float wrap_torus(float x) {
    const float PI_F     = 3.14159274101257324f;
    const float TWO_PI_F = 6.28318548202514648f;
    float t = __fadd_rn(x, PI_F);
    if (t >= TWO_PI_F) t = __fsub_rn(t, TWO_PI_F);
    if (t < 0.0f)      t = __fadd_rn(t, TWO_PI_F);
    return __fsub_rn(t, PI_F);
}

__device__ __forceinline__ void cp16(float* dst_smem, const float* src) {
    unsigned s = (unsigned)__cvta_generic_to_shared(dst_smem);
    asm volatile("cp.async.cg.shared.global [%0], [%1], 16;" :: "r"(s), "l"(src));
}
#define CP_COMMIT() asm volatile("cp.async.commit_group;")
#define CP_WAIT1()  asm volatile("cp.async.wait_group 1;")
#define CP_WAIT0()  asm volatile("cp.async.wait_group 0;")

__global__ __launch_bounds__(THREADS, 1)
void fr_kernel(const float* __restrict__ gx, const float* __restrict__ gv,
               const float* __restrict__ gf, const float* __restrict__ gU,
               const float* __restrict__ gW, const int* __restrict__ gsteps,
               float* __restrict__ gox, float* __restrict__ gov)
{
    extern __shared__ float smem[];
    float* sh    = smem;                 // h0 [32][64]        2048 f
    float* sfU   = sh   + 2048;          // fU [32][64]        2048 f
    float* kbuf  = sfU  + 2048;          // evals: 2x[32][H2DS]=8448; epi: stv+stx 4608 (alias)
    float* sWU   = kbuf + 8448;          // [64][WUS]          4352 f
    float* spart = sWU  + 4352;          // merge scratch      8192 f
    float* stage = spart + 8192;         // 2 x STAGE_N       16896 f

    const int tid  = threadIdx.x;
    const int wid  = tid >> 5;
    const int lane = tid & 31;
    const int row0 = blockIdx.x * CTA_M;
    const int er = tid >> 4;            // eval row
    const int ec = (tid & 15) * 4;      // eval cols ec..ec+3
    const int g  = wid >> 2;            // epi rows 8g..8g+7
    const int cc = (wid >> 1) & 1;      // epi chunk parity
    const int ks = wid & 1;             // epi k-half

    auto issueUT = [&](int c) {          // U^T chunk c: [64 k][128 d], stride UTS
        float* dst = stage + (c & 1) * STAGE_N;
        const float* src = g_UT + c * 128;
        #pragma unroll
        for (int i = 0; i < 4; ++i) {
            int idx = tid + i * THREADS;          // 0..2047 16B units
            int k = idx >> 5, dl = (idx & 31) * 4;
            cp16(dst + k * UTS + dl, src + (size_t)k * DDIM + dl);
        }
        CP_COMMIT();
    };
    auto issueW = [&](int c) {           // W col-chunk c: [64 k][128 c], stride 128
        float* dst = stage + (c & 1) * STAGE_N;
        const float* src = gW + c * 128;
        #pragma unroll
        for (int i = 0; i < 4; ++i) {
            int idx = tid + i * THREADS;
            int k = idx >> 5, seg = (idx & 31) * 4;
            cp16(dst + k * 128 + seg, src + (size_t)k * DDIM + seg);
        }
        CP_COMMIT();
    };

    issueUT(0); issueUT(1);
    {
        #pragma unroll
        for (int i = 0; i < 8; ++i) {
            int idx = tid + i * THREADS;          // 4096 WU elements
            sWU[(idx >> 6) * WUS + (idx & 63)] = g_WU[idx];
        }
    }
    __syncthreads();

    const int steps = gsteps ? gsteps[0] : 4;

    // ---- prologue: h0 = v@U, fU = f@U; d-pair FFMA2 against U^T ----
    {
        ull hA0 = 0, hA1 = 0, hB0 = 0, hB1 = 0;     // {even-d,odd-d} partial pairs
        ull fA0 = 0, fA1 = 0, fB0 = 0, fB1 = 0;
        const int pr0 = 2 * wid, pr1 = 2 * wid + 1;
        const int k0 = 2 * lane, k1 = 2 * lane + 1;
        #pragma unroll 1
        for (int c = 0; c < 4; ++c) {
            if (c < 3) { CP_WAIT1(); } else { CP_WAIT0(); }
            __syncthreads();
            const float* sU = stage + (c & 1) * STAGE_N;
            const ulonglong2* pv0 = (const ulonglong2*)(gv + (size_t)(row0 + pr0) * DDIM + c * 128);
            const ulonglong2* pv1 = (const ulonglong2*)(gv + (size_t)(row0 + pr1) * DDIM + c * 128);
            const ulonglong2* pf0 = (const ulonglong2*)(gf + (size_t)(row0 + pr0) * DDIM + c * 128);
            const ulonglong2* pf1 = (const ulonglong2*)(gf + (size_t)(row0 + pr1) * DDIM + c * 128);
            const float* u0b = sU + k0 * UTS;
            const float* u1b = sU + k1 * UTS;
            #pragma unroll 4
            for (int d4 = 0; d4 < 32; ++d4) {
                ulonglong2 v0 = pv0[d4];
                ulonglong2 v1 = pv1[d4];
                ulonglong2 f0 = pf0[d4];
                ulonglong2 f1 = pf1[d4];
                ulonglong2 u0 = *(const ulonglong2*)(u0b + d4 * 4);
                ulonglong2 u1 = *(const ulonglong2*)(u1b + d4 * 4);
                fma2(hA0, v0.x, u0.x); fma2(hA0, v0.y, u0.y);
                fma2(hA1, v0.x, u1.x); fma2(hA1, v0.y, u1.y);
                fma2(hB0, v1.x, u0.x); fma2(hB0, v1.y, u0.y);
                fma2(hB1, v1.x, u1.x); fma2(hB1, v1.y, u1.y);
                fma2(fA0, f0.x, u0.x); fma2(fA0, f0.y, u0.y);
                fma2(fA1, f0.x, u1.x); fma2(fA1, f0.y, u1.y);
                fma2(fB0, f1.x, u0.x); fma2(fB0, f1.y, u0.y);
                fma2(fB1, f1.x, u1.x); fma2(fB1, f1.y, u1.y);
            }
            __syncthreads();
            if (c < 2) issueUT(c + 2);
        }
        float2 t;
        t = unpack2(hA0); sh[pr0 * KDIM + k0] = __fadd_rn(t.x, t.y);
        t = unpack2(hA1); sh[pr0 * KDIM + k1] = __fadd_rn(t.x, t.y);
        t = unpack2(hB0); sh[pr1 * KDIM + k0] = __fadd_rn(t.x, t.y);
        t = unpack2(hB1); sh[pr1 * KDIM + k1] = __fadd_rn(t.x, t.y);
        t = unpack2(fA0); sfU[pr0 * KDIM + k0] = __fadd_rn(t.x, t.y);
        t = unpack2(fA1); sfU[pr0 * KDIM + k1] = __fadd_rn(t.x, t.y);
        t = unpack2(fB0); sfU[pr1 * KDIM + k0] = __fadd_rn(t.x, t.y);
        t = unpack2(fB1); sfU[pr1 * KDIM + k1] = __fadd_rn(t.x, t.y);
    }
    issueW(0); issueW(1);                 // epilogue W rides through all evals
    __syncthreads();

    // per-thread K-space state
    float4 h  = *(const float4*)(sh  + er * KDIM + ec);
    float4 fU = *(const float4*)(sfU + er * KDIM + ec);
    float4 Sv = make_float4(0.f, 0.f, 0.f, 0.f);
    float4 Sx = make_float4(0.f, 0.f, 0.f, 0.f);

    const double TH = 1.0 / (2.0 - cbrt(2.0));
    const float d1dtF = (float)(TH * 0.01);
    const float d2dtF = (float)((1.0 - 2.0 * TH) * 0.01);
    const float wv1 = (float)TH;
    const float wv2 = (float)(1.0 - 2.0 * TH);
    double Gam = 0.0;
    for (int s = 0; s < steps; ++s) {
        double R = (double)(steps - 1 - s);
        Gam += TH * (1.0 - 0.5 * TH + R) + (1.0 - 2.0 * TH) * (0.5 + R) + TH * (0.5 * TH + R);
    }

    int p = 0;
    auto evalstep = [&](float ddt, float wv, float wx) {
        float* h2b = kbuf + p * (CTA_M * H2DS);
        float4 h2;
        h2.x = __fmul_rn(h.x, h.x); h2.y = __fmul_rn(h.y, h.y);
        h2.z = __fmul_rn(h.z, h.z); h2.w = __fmul_rn(h.w, h.w);
        *(float4*)(h2b + er * H2DS + 2 * ec)     = make_float4(h2.x, h2.x, h2.y, h2.y);
        *(float4*)(h2b + er * H2DS + 2 * ec + 4) = make_float4(h2.z, h2.z, h2.w, h2.w);
        __syncthreads();
        ull outA = 0, outB = 0;
        const float* hr = h2b + er * H2DS;
        const float* wc = sWU + ec;
        #pragma unroll 8
        for (int kin = 0; kin < KDIM; ++kin) {
            ull hd = *(const ull*)(hr + 2 * kin);
            ulonglong2 wu = *(const ulonglong2*)(wc + kin * WUS);
            fma2(outA, hd, wu.x);
            fma2(outB, hd, wu.y);
        }
        float2 oA = unpack2(outA), oB = unpack2(outB);
        Sv.x = fmaf(wv, h2.x, Sv.x); Sv.y = fmaf(wv, h2.y, Sv.y);
        Sv.z = fmaf(wv, h2.z, Sv.z); Sv.w = fmaf(wv, h2.w, Sv.w);
        Sx.x = fmaf(wx, h2.x, Sx.x); Sx.y = fmaf(wx, h2.y, Sx.y);
        Sx.z = fmaf(wx, h2.z, Sx.z); Sx.w = fmaf(wx, h2.w, Sx.w);
        h.x = __fadd_rn(h.x, __fmul_rn(ddt, __fadd_rn(-oA.x, fU.x)));
        h.y = __fadd_rn(h.y, __fmul_rn(ddt, __fadd_rn(-oA.y, fU.y)));
        h.z = __fadd_rn(h.z, __fmul_rn(ddt, __fadd_rn(-oB.x, fU.z)));
        h.w = __fadd_rn(h.w, __fmul_rn(ddt, __fadd_rn(-oB.y, fU.w)));
        p ^= 1;
    };

    for (int s = 0; s < steps; ++s) {
        double R = (double)(steps - 1 - s);
        float wx1 = (float)(TH * (1.0 - 0.5 * TH + R));
        float wx2 = (float)((1.0 - 2.0 * TH) * (0.5 + R));
        float wx3 = (float)(TH * (0.5 * TH + R));
        evalstep(d1dtF, wv1, wx1);
        evalstep(d2dtF, wv2, wx2);
        evalstep(d1dtF, wv1, wx3);
    }

    // ---- epilogue ----
    __syncthreads();                      // all eval reads of kbuf done
    float* stv = kbuf;                    // [64][STS_]
    float* stx = kbuf + KDIM * STS_;
    stv[(ec + 0) * STS_ + er] = Sv.x; stv[(ec + 1) * STS_ + er] = Sv.y;
    stv[(ec + 2) * STS_ + er] = Sv.z; stv[(ec + 3) * STS_ + er] = Sv.w;
    stx[(ec + 0) * STS_ + er] = Sx.x; stx[(ec + 1) * STS_ + er] = Sx.y;
    stx[(ec + 2) * STS_ + er] = Sx.z; stx[(ec + 3) * STS_ + er] = Sx.w;

    const float dtF      = 0.01f;
    const float dt2F     = 1e-4f;
    const float stepsF   = (float)steps;
    const float stepsdtF = (float)((double)steps * 0.01);
    const float GamF     = (float)Gam;

    float* sp = spart + (g * 2 + cc) * 1024;

    #pragma unroll 1
    for (int P = 0; P < 2; ++P) {
        CP_WAIT0(); __syncthreads();
        const float* sWc = stage + cc * STAGE_N;
        const float* wb  = sWc + lane * 4 + ks * 32 * 128;
        const int col = (2 * P + cc) * 128 + lane * 4;

        #pragma unroll 1
        for (int M = 0; M < 2; ++M) {     // M=0: v-pass (stv), M=1: x-pass (stx)
            const float* sb = (M == 0 ? stv : stx) + 8 * g + ks * 32 * STS_;
            ull A[4][4];
            #pragma unroll
            for (int rp = 0; rp < 4; ++rp)
                #pragma unroll
                for (int c = 0; c < 4; ++c) A[rp][c] = 0;
            #pragma unroll 4
            for (int k = 0; k < 32; ++k) {
                float4 w4 = *(const float4*)(wb + k * 128);
                ulonglong2 sA = *(const ulonglong2*)(sb + k * STS_);
                ulonglong2 sB = *(const ulonglong2*)(sb + k * STS_ + 4);
                ull w0 = packdup(w4.x), w1 = packdup(w4.y);
                ull w2 = packdup(w4.z), w3 = packdup(w4.w);
                fma2(A[0][0], sA.x, w0); fma2(A[0][1], sA.x, w1);
                fma2(A[0][2], sA.x, w2); fma2(A[0][3], sA.x, w3);
                fma2(A[1][0], sA.y, w0); fma2(A[1][1], sA.y, w1);
                fma2(A[1][2], sA.y, w2); fma2(A[1][3], sA.y, w3);
                fma2(A[2][0], sB.x, w0); fma2(A[2][1], sB.x, w1);
                fma2(A[2][2], sB.x, w2); fma2(A[2][3], sB.x, w3);
                fma2(A[3][0], sB.y, w0); fma2(A[3][1], sB.y, w1);
                fma2(A[3][2], sB.y, w2); fma2(A[3][3], sB.y, w3);
            }
            if (ks == 1) {
                #pragma unroll
                for (int rp = 0; rp < 4; ++rp) {
                    *(ulonglong2*)(sp + rp * 256 + lane * 8)     = make_ulonglong2(A[rp][0], A[rp][1]);
                    *(ulonglong2*)(sp + rp * 256 + lane * 8 + 4) = make_ulonglong2(A[rp][2], A[rp][3]);
                }
            }
            __syncthreads();
            if (P == 0 && M == 1) { issueW(2); issueW(3); }  // all chunk reads done
            if (ks == 0) {
                #pragma unroll
                for (int rp = 0; rp < 4; ++rp) {
                    ulonglong2 q0 = *(const ulonglong2*)(sp + rp * 256 + lane * 8);
                    ulonglong2 q1 = *(const ulonglong2*)(sp + rp * 256 + lane * 8 + 4);
                    float2 m0 = unpack2(add2(A[rp][0], q0.x));
                    float2 m1 = unpack2(add2(A[rp][1], q0.y));
                    float2 m2 = unpack2(add2(A[rp][2], q1.x));
                    float2 m3 = unpack2(add2(A[rp][3], q1.y));
                    #pragma unroll
                    for (int hh = 0; hh < 2; ++hh) {
                        const int r = 8 * g + 2 * rp + hh;
                        float c0 = hh ? m0.y : m0.x, c1 = hh ? m1.y : m1.x;
                        float c2 = hh ? m2.y : m2.x, c3 = hh ? m3.y : m3.x;
                        float4 fv = *(const float4*)(gf + (size_t)(row0 + r) * DDIM + col);
                        float4 v0 = *(const float4*)(gv + (size_t)(row0 + r) * DDIM + col);
                        if (M == 0) {     // v = v0 + dt*(-Gv + steps*f)
                            float4 vo;
                            vo.x = __fadd_rn(v0.x, __fmul_rn(dtF, __fadd_rn(-c0, __fmul_rn(stepsF, fv.x))));
                            vo.y = __fadd_rn(v0.y, __fmul_rn(dtF, __fadd_rn(-c1, __fmul_rn(stepsF, fv.y))));
                            vo.z = __fadd_rn(v0.z, __fmul_rn(dtF, __fadd_rn(-c2, __fmul_rn(stepsF, fv.z))));
                            vo.w = __fadd_rn(v0.w, __fmul_rn(dtF, __fadd_rn(-c3, __fmul_rn(stepsF, fv.w))));
                            *(float4*)(gov + (size_t)(row0 + r) * DDIM + col) = vo;
                        } else {          // x = wrap(x0 + steps*dt*v0 + dt^2*(-Gx + Gam*f))
                            float4 x0 = *(const float4*)(gx + (size_t)(row0 + r) * DDIM + col);
                            float4 xo;
                            xo.x = __fadd_rn(fmaf(stepsdtF, v0.x, x0.x),
                                             __fmul_rn(dt2F, __fadd_rn(-c0, __fmul_rn(GamF, fv.x))));
                            xo.y = __fadd_rn(fmaf(stepsdtF, v0.y, x0.y),
                                             __fmul_rn(dt2F, __fadd_rn(-c1, __fmul_rn(GamF, fv.y))));
                            xo.z = __fadd_rn(fmaf(stepsdtF, v0.z, x0.z),
                                             __fmul_rn(dt2F, __fadd_rn(-c2, __fmul_rn(GamF, fv.z))));
                            xo.w = __fadd_rn(fmaf(stepsdtF, v0.w, x0.w),
                                             __fmul_rn(dt2F, __fadd_rn(-c3, __fmul_rn(GamF, fv.w))));
                            if (steps != 0) {
                                xo.x = wrap_torus(xo.x); xo.y = wrap_torus(xo.y);
                                xo.z = wrap_torus(xo.z); xo.w = wrap_torus(xo.w);
                            }
                            *(float4*)(gox + (size_t)(row0 + r) * DDIM + col) = xo;
                        }
                    }
                }
            }
            __syncthreads();              // spart reuse between M passes / P phases
        }
    }
    CP_WAIT0();
}

extern "C" void kernel_launch(void* const* d_in, const int* in_sizes, int n_in,
                              void* d_out, int out_size)
{
    const float* x = (const float*)d_in[0];
    const float* v = (const float*)d_in[1];
    const float* f = (const float*)d_in[2];
    const float* U = (const float*)d_in[3];
    const float* W = (const float*)d_in[4];
    const int* steps = (n_in >= 6) ? (const int*)d_in[5] : nullptr;

    const int B  = in_sizes[0] / DDIM;
    const int BD = B * DDIM;
    float* ox = (float*)d_out;
    float* ov = ox + BD;

    wu_kernel<<<16, 256>>>(W, U);
    ut_kernel<<<64, 512>>>(U);

    const int smem_floats = 2048 + 2048 + 8448 + 4352 + 8192 + 2 * STAGE_N;  // 41984
    const int smem_bytes = smem_floats * 4;                                  // 167,936
    cudaFuncSetAttribute(fr_kernel, cudaFuncAttributeMaxDynamicSharedMemorySize, smem_bytes);
    fr_kernel<<<B / CTA_M, THREADS, smem_bytes>>>(x, v, f, U, W, steps, ox, ov);
}

// round 13
// speedup vs baseline: 1.2077x; 1.2077x over previous
#include <cuda_runtime.h>
#include <math.h>

// ForestRuthIntegrator v6 — K-space trajectory (v4 math), occupancy-2 layout.
// smem 85KB/CTA -> 2 CTAs/SM. No sv staging, no spart (epilogue 2rows x 4cols
// x full-k per thread), single 32KB stage (U: 2x16KB ping-pong, W: 4 phases).
// wu_kernel parallelized (64 blocks).

#define THREADS 512
#define CTA_M   32
#define DDIM    512
#define KDIM    64
#define WUS     68      // WU row stride
#define H2SS    68      // eval h^2 row stride
#define STS_    36      // transposed-S stride

__device__ float g_WU[KDIM * KDIM];

__global__ void wu_kernel(const float* __restrict__ gW, const float* __restrict__ gU) {
    // one output row a per block; 64 threads = b; 4 independent partials
    const int a = blockIdx.x, b = threadIdx.x;
    const float* wr = gW + a * DDIM;
    float s0 = 0.f, s1 = 0.f, s2 = 0.f, s3 = 0.f;
    #pragma unroll 4
    for (int d = 0; d < DDIM; d += 4) {
        s0 = fmaf(wr[d + 0], gU[(d + 0) * KDIM + b], s0);
        s1 = fmaf(wr[d + 1], gU[(d + 1) * KDIM + b], s1);
        s2 = fmaf(wr[d + 2], gU[(d + 2) * KDIM + b], s2);
        s3 = fmaf(wr[d + 3], gU[(d + 3) * KDIM + b], s3);
    }
    g_WU[a * KDIM + b] = __fadd_rn(__fadd_rn(s0, s1), __fadd_rn(s2, s3));
}

__device__ __forceinline__ float wrap_torus(float x) {
    const float PI_F     = 3.14159274101257324f;
    const float TWO_PI_F = 6.28318548202514648f;
    float t = __fadd_rn(x, PI_F);
    if (t >= TWO_PI_F) t = __fsub_rn(t, TWO_PI_F);
    if (t < 0.0f)      t = __fadd_rn(t, TWO_PI_F);
    return __fsub_rn(t, PI_F);
}

__device__ __forceinline__ void cp16(float* dst_smem, const float* src) {
    unsigned s = (unsigned)__cvta_generic_to_shared(dst_smem);
    asm volatile("cp.async.cg.shared.global [%0], [%1], 16;" :: "r"(s), "l"(src));
}
#define CP_COMMIT() asm volatile("cp.async.commit_group;")
#define CP_WAIT1()  asm volatile("cp.async.wait_group 1;")
#define CP_WAIT0()  asm volatile("cp.async.wait_group 0;")

__global__ __launch_bounds__(THREADS, 2)
void fr_kernel(const float* __restrict__ gx, const float* __restrict__ gv,
               const float* __restrict__ gf, const float* __restrict__ gU,
               const float* __restrict__ gW, const int* __restrict__ gsteps,
               float* __restrict__ gox, float* __restrict__ gov)
{
    extern __shared__ float smem[];
    float* sh    = smem;                 // h0 [32][64]                    2048 f
    float* sfU   = sh   + 2048;          // fU [32][64]                    2048 f
    float* kbuf  = sfU  + 2048;          // evals 2x[32][68]; epi stv+stx  4608 f
    float* sWU   = kbuf + 4608;          // [64][WUS]                      4352 f
    float* stage = sWU  + 4352;          // U: 2x4096 ping-pong / W: 8192  8192 f
                                         // total 21248 f = 84,992 B -> 2 CTAs/SM

    const int tid  = threadIdx.x;
    const int wid  = tid >> 5;
    const int lane = tid & 31;
    const int row0 = blockIdx.x * CTA_M;
    const int er = tid >> 4;            // eval row
    const int ec = (tid & 15) * 4;      // eval cols ec..ec+3
    const int r0 = 2 * wid, r1 = 2 * wid + 1;   // prologue/epilogue rows

    auto issueU = [&](int c) {           // U rows [64c..64c+64) -> stage half (c&1)
        float* dst = stage + (c & 1) * 4096;
        const float* src = gU + (size_t)c * 4096;
        #pragma unroll
        for (int i = 0; i < 2; ++i) { int idx = tid + i * THREADS; cp16(dst + idx * 4, src + idx * 4); }
        CP_COMMIT();
    };
    auto issueW = [&](int c) {           // W col-chunk c: [64 k][128 cols] -> full stage
        const float* src = gW + c * 128;
        #pragma unroll
        for (int i = 0; i < 4; ++i) {
            int idx = tid + i * THREADS;
            int k = idx >> 5, seg = (idx & 31) * 4;
            cp16(stage + k * 128 + seg, src + (size_t)k * DDIM + seg);
        }
        CP_COMMIT();
    };

    issueU(0); issueU(1);
    #pragma unroll
    for (int i = 0; i < 8; ++i) {        // WU -> smem
        int idx = tid + i * THREADS;
        sWU[(idx >> 6) * WUS + (idx & 63)] = g_WU[idx];
    }
    __syncthreads();

    const int steps = gsteps ? gsteps[0] : 4;

    // ---- prologue: h0 = v@U, fU = f@U; 2 rows/warp, k-pair/lane; 8 chunks ----
    {
        float ah00=0.f, ah01=0.f, ah10=0.f, ah11=0.f;
        float af00=0.f, af01=0.f, af10=0.f, af11=0.f;
        #pragma unroll 1
        for (int c = 0; c < 8; ++c) {
            if (c < 7) { CP_WAIT1(); } else { CP_WAIT0(); }
            __syncthreads();
            const float* sU = stage + (c & 1) * 4096;
            const float* p0 = gv + (size_t)(row0 + r0) * DDIM + c * 64;
            const float* p1 = gv + (size_t)(row0 + r1) * DDIM + c * 64;
            const float* q0 = gf + (size_t)(row0 + r0) * DDIM + c * 64;
            const float* q1 = gf + (size_t)(row0 + r1) * DDIM + c * 64;
            const float* ub = sU + 2 * lane;
            #pragma unroll 4
            for (int d4 = 0; d4 < 16; ++d4) {
                float4 v0 = *(const float4*)(p0 + d4 * 4);
                float4 v1 = *(const float4*)(p1 + d4 * 4);
                float4 f0 = *(const float4*)(q0 + d4 * 4);
                float4 f1 = *(const float4*)(q1 + d4 * 4);
                const float* u = ub + (d4 * 4) * KDIM;
                float2 t;
                t = *(const float2*)(u);
                ah00 = fmaf(v0.x, t.x, ah00); ah01 = fmaf(v0.x, t.y, ah01);
                ah10 = fmaf(v1.x, t.x, ah10); ah11 = fmaf(v1.x, t.y, ah11);
                af00 = fmaf(f0.x, t.x, af00); af01 = fmaf(f0.x, t.y, af01);
                af10 = fmaf(f1.x, t.x, af10); af11 = fmaf(f1.x, t.y, af11);
                t = *(const float2*)(u + KDIM);
                ah00 = fmaf(v0.y, t.x, ah00); ah01 = fmaf(v0.y, t.y, ah01);
                ah10 = fmaf(v1.y, t.x, ah10); ah11 = fmaf(v1.y, t.y, ah11);
                af00 = fmaf(f0.y, t.x, af00); af01 = fmaf(f0.y, t.y, af01);
                af10 = fmaf(f1.y, t.x, af10); af11 = fmaf(f1.y, t.y, af11);
                t = *(const float2*)(u + 2 * KDIM);
                ah00 = fmaf(v0.z, t.x, ah00); ah01 = fmaf(v0.z, t.y, ah01);
                ah10 = fmaf(v1.z, t.x, ah10); ah11 = fmaf(v1.z, t.y, ah11);
                af00 = fmaf(f0.z, t.x, af00); af01 = fmaf(f0.z, t.y, af01);
                af10 = fmaf(f1.z, t.x, af10); af11 = fmaf(f1.z, t.y, af11);
                t = *(const float2*)(u + 3 * KDIM);
                ah00 = fmaf(v0.w, t.x, ah00); ah01 = fmaf(v0.w, t.y, ah01);
                ah10 = fmaf(v1.w, t.x, ah10); ah11 = fmaf(v1.w, t.y, ah11);
                af00 = fmaf(f0.w, t.x, af00); af01 = fmaf(f0.w, t.y, af01);
                af10 = fmaf(f1.w, t.x, af10); af11 = fmaf(f1.w, t.y, af11);
            }
            __syncthreads();
            if (c < 6) issueU(c + 2);
        }
        sh[r0 * KDIM + 2 * lane]     = ah00; sh[r0 * KDIM + 2 * lane + 1] = ah01;
        sh[r1 * KDIM + 2 * lane]     = ah10; sh[r1 * KDIM + 2 * lane + 1] = ah11;
        sfU[r0 * KDIM + 2 * lane]     = af00; sfU[r0 * KDIM + 2 * lane + 1] = af01;
        sfU[r1 * KDIM + 2 * lane]     = af10; sfU[r1 * KDIM + 2 * lane + 1] = af11;
    }
    issueW(0);                            // epilogue chunk 0 rides through evals
    __syncthreads();

    // per-thread K-space state
    float4 h  = *(const float4*)(sh  + er * KDIM + ec);
    float4 fU = *(const float4*)(sfU + er * KDIM + ec);
    float4 Sv = make_float4(0.f, 0.f, 0.f, 0.f);
    float4 Sx = make_float4(0.f, 0.f, 0.f, 0.f);

    const double TH = 1.0 / (2.0 - cbrt(2.0));
    const float d1dtF = (float)(TH * 0.01);
    const float d2dtF = (float)((1.0 - 2.0 * TH) * 0.01);
    const float wv1 = (float)TH;
    const float wv2 = (float)(1.0 - 2.0 * TH);
    double Gam = 0.0;
    for (int s = 0; s < steps; ++s) {
        double R = (double)(steps - 1 - s);
        Gam += TH * (1.0 - 0.5 * TH + R) + (1.0 - 2.0 * TH) * (0.5 + R) + TH * (0.5 * TH + R);
    }

    int p = 0;
    auto evalstep = [&](float ddt, float wv, float wx) {
        float* h2b = kbuf + p * 2176;
        float4 h2;
        h2.x = __fmul_rn(h.x, h.x); h2.y = __fmul_rn(h.y, h.y);
        h2.z = __fmul_rn(h.z, h.z); h2.w = __fmul_rn(h.w, h.w);
        *(float4*)(h2b + er * H2SS + ec) = h2;
        __syncthreads();
        float4 out = make_float4(0.f, 0.f, 0.f, 0.f);
        const float* hr = h2b + er * H2SS;
        const float* wc = sWU + ec;
        #pragma unroll 8
        for (int kin = 0; kin < KDIM; ++kin) {
            float hv = hr[kin];
            float4 wu = *(const float4*)(wc + kin * WUS);
            out.x = fmaf(hv, wu.x, out.x);
            out.y = fmaf(hv, wu.y, out.y);
            out.z = fmaf(hv, wu.z, out.z);
            out.w = fmaf(hv, wu.w, out.w);
        }
        Sv.x = fmaf(wv, h2.x, Sv.x); Sv.y = fmaf(wv, h2.y, Sv.y);
        Sv.z = fmaf(wv, h2.z, Sv.z); Sv.w = fmaf(wv, h2.w, Sv.w);
        Sx.x = fmaf(wx, h2.x, Sx.x); Sx.y = fmaf(wx, h2.y, Sx.y);
        Sx.z = fmaf(wx, h2.z, Sx.z); Sx.w = fmaf(wx, h2.w, Sx.w);
        h.x = __fadd_rn(h.x, __fmul_rn(ddt, __fadd_rn(-out.x, fU.x)));
        h.y = __fadd_rn(h.y, __fmul_rn(ddt, __fadd_rn(-out.y, fU.y)));
        h.z = __fadd_rn(h.z, __fmul_rn(ddt, __fadd_rn(-out.z, fU.z)));
        h.w = __fadd_rn(h.w, __fmul_rn(ddt, __fadd_rn(-out.w, fU.w)));
        p ^= 1;
    };

    for (int s = 0; s < steps; ++s) {
        double R = (double)(steps - 1 - s);
        float wx1 = (float)(TH * (1.0 - 0.5 * TH + R));
        float wx2 = (float)((1.0 - 2.0 * TH) * (0.5 + R));
        float wx3 = (float)(TH * (0.5 * TH + R));
        evalstep(d1dtF, wv1, wx1);
        evalstep(d2dtF, wv2, wx2);
        evalstep(d1dtF, wv1, wx3);
    }

    // ---- epilogue: Gv=Sv@W, Gx=Sx@W; 2 rows x 4 cols x full-k per thread ----
    __syncthreads();                      // all eval reads of kbuf done
    float* stv = kbuf;                    // [64][STS_]
    float* stx = kbuf + KDIM * STS_;
    stv[(ec + 0) * STS_ + er] = Sv.x; stv[(ec + 1) * STS_ + er] = Sv.y;
    stv[(ec + 2) * STS_ + er] = Sv.z; stv[(ec + 3) * STS_ + er] = Sv.w;
    stx[(ec + 0) * STS_ + er] = Sx.x; stx[(ec + 1) * STS_ + er] = Sx.y;
    stx[(ec + 2) * STS_ + er] = Sx.z; stx[(ec + 3) * STS_ + er] = Sx.w;

    const float dtF      = 0.01f;
    const float dt2F     = 1e-4f;
    const float stepsF   = (float)steps;
    const float stepsdtF = (float)((double)steps * 0.01);
    const float GamF     = (float)Gam;

    #pragma unroll 1
    for (int P = 0; P < 4; ++P) {
        CP_WAIT0(); __syncthreads();
        const float* wb = stage + lane * 4;
        const int col = P * 128 + lane * 4;

        // v-pass: Gv rows r0,r1
        {
            float4 A0 = make_float4(0.f,0.f,0.f,0.f), A1 = make_float4(0.f,0.f,0.f,0.f);
            const float* sb = stv + r0;
            #pragma unroll 8
            for (int k = 0; k < KDIM; ++k) {
                float4 w4 = *(const float4*)(wb + k * 128);
                float2 sq = *(const float2*)(sb + k * STS_);
                A0.x = fmaf(sq.x, w4.x, A0.x); A0.y = fmaf(sq.x, w4.y, A0.y);
                A0.z = fmaf(sq.x, w4.z, A0.z); A0.w = fmaf(sq.x, w4.w, A0.w);
                A1.x = fmaf(sq.y, w4.x, A1.x); A1.y = fmaf(sq.y, w4.y, A1.y);
                A1.z = fmaf(sq.y, w4.z, A1.z); A1.w = fmaf(sq.y, w4.w, A1.w);
            }
            #pragma unroll
            for (int i = 0; i < 2; ++i) {
                const int r = r0 + i;
                const float4 G = i ? A1 : A0;
                float4 fv = *(const float4*)(gf + (size_t)(row0 + r) * DDIM + col);
                float4 v0 = *(const float4*)(gv + (size_t)(row0 + r) * DDIM + col);
                float4 vo;
                vo.x = __fadd_rn(v0.x, __fmul_rn(dtF, __fadd_rn(-G.x, __fmul_rn(stepsF, fv.x))));
                vo.y = __fadd_rn(v0.y, __fmul_rn(dtF, __fadd_rn(-G.y, __fmul_rn(stepsF, fv.y))));
                vo.z = __fadd_rn(v0.z, __fmul_rn(dtF, __fadd_rn(-G.z, __fmul_rn(stepsF, fv.z))));
                vo.w = __fadd_rn(v0.w, __fmul_rn(dtF, __fadd_rn(-G.w, __fmul_rn(stepsF, fv.w))));
                *(float4*)(gov + (size_t)(row0 + r) * DDIM + col) = vo;
            }
        }
        // x-pass: Gx rows r0,r1
        {
            float4 A0 = make_float4(0.f,0.f,0.f,0.f), A1 = make_float4(0.f,0.f,0.f,0.f);
            const float* sb = stx + r0;
            #pragma unroll 8
            for (int k = 0; k < KDIM; ++k) {
                float4 w4 = *(const float4*)(wb + k * 128);
                float2 sq = *(const float2*)(sb + k * STS_);
                A0.x = fmaf(sq.x, w4.x, A0.x); A0.y = fmaf(sq.x, w4.y, A0.y);
                A0.z = fmaf(sq.x, w4.z, A0.z); A0.w = fmaf(sq.x, w4.w, A0.w);
                A1.x = fmaf(sq.y, w4.x, A1.x); A1.y = fmaf(sq.y, w4.y, A1.y);
                A1.z = fmaf(sq.y, w4.z, A1.z); A1.w = fmaf(sq.y, w4.w, A1.w);
            }
            #pragma unroll
            for (int i = 0; i < 2; ++i) {
                const int r = r0 + i;
                const float4 G = i ? A1 : A0;
                float4 fv = *(const float4*)(gf + (size_t)(row0 + r) * DDIM + col);
                float4 v0 = *(const float4*)(gv + (size_t)(row0 + r) * DDIM + col);
                float4 x0 = *(const float4*)(gx + (size_t)(row0 + r) * DDIM + col);
                float4 xo;
                xo.x = __fadd_rn(fmaf(stepsdtF, v0.x, x0.x),
                                 __fmul_rn(dt2F, __fadd_rn(-G.x, __fmul_rn(GamF, fv.x))));
                xo.y = __fadd_rn(fmaf(stepsdtF, v0.y, x0.y),
                                 __fmul_rn(dt2F, __fadd_rn(-G.y, __fmul_rn(GamF, fv.y))));
                xo.z = __fadd_rn(fmaf(stepsdtF, v0.z, x0.z),
                                 __fmul_rn(dt2F, __fadd_rn(-G.z, __fmul_rn(GamF, fv.z))));
                xo.w = __fadd_rn(fmaf(stepsdtF, v0.w, x0.w),
                                 __fmul_rn(dt2F, __fadd_rn(-G.w, __fmul_rn(GamF, fv.w))));
                if (steps != 0) {
                    xo.x = wrap_torus(xo.x); xo.y = wrap_torus(xo.y);
                    xo.z = wrap_torus(xo.z); xo.w = wrap_torus(xo.w);
                }
                *(float4*)(gox + (size_t)(row0 + r) * DDIM + col) = xo;
            }
        }
        __syncthreads();                  // chunk fully consumed
        if (P < 3) issueW(P + 1);
    }
    CP_WAIT0();
}

extern "C" void kernel_launch(void* const* d_in, const int* in_sizes, int n_in,
                              void* d_out, int out_size)
{
    const float* x = (const float*)d_in[0];
    const float* v = (const float*)d_in[1];
    const float* f = (const float*)d_in[2];
    const float* U = (const float*)d_in[3];
    const float* W = (const float*)d_in[4];
    const int* steps = (n_in >= 6) ? (const int*)d_in[5] : nullptr;

    const int B  = in_sizes[0] / DDIM;
    const int BD = B * DDIM;
    float* ox = (float*)d_out;
    float* ov = ox + BD;

    wu_kernel<<<KDIM, KDIM>>>(W, U);

    const int smem_floats = 2048 + 2048 + 4608 + 4352 + 8192;  // 21248
    const int smem_bytes = smem_floats * 4;                    // 84,992 B
    cudaFuncSetAttribute(fr_kernel, cudaFuncAttributeMaxDynamicSharedMemorySize, smem_bytes);
    fr_kernel<<<B / CTA_M, THREADS, smem_bytes>>>(x, v, f, U, W, steps, ox, ov);
}

// round 15
// speedup vs baseline: 1.2150x; 1.0060x over previous
#include <cuda_runtime.h>
#include <math.h>

// ForestRuthIntegrator v7 — v6 math, square warp tiles to cut smem crossbar.
// Prologue: warp 8r x 16k (thread 1x4). Eval: warp 8r x 16c (thread 2x2),
// h^2 transposed [kin][row]. Epilogue: warp 16r x 32c (thread 2x8), v/x pass
// parallel across warps. All per-element accumulation orders == v6 (bitwise).

#define THREADS 512
#define CTA_M   32
#define DDIM    512
#define KDIM    64
#define WUS     66      // WU row stride (even, float2-aligned)
#define H2TS    34      // transposed h^2 / S stride (even)

__device__ float g_WU[KDIM * KDIM];

__global__ void wu_kernel(const float* __restrict__ gW, const float* __restrict__ gU) {
    const int a = blockIdx.x, b = threadIdx.x;
    const float* wr = gW + a * DDIM;
    float s0 = 0.f, s1 = 0.f, s2 = 0.f, s3 = 0.f;
    #pragma unroll 4
    for (int d = 0; d < DDIM; d += 4) {
        s0 = fmaf(wr[d + 0], gU[(d + 0) * KDIM + b], s0);
        s1 = fmaf(wr[d + 1], gU[(d + 1) * KDIM + b], s1);
        s2 = fmaf(wr[d + 2], gU[(d + 2) * KDIM + b], s2);
        s3 = fmaf(wr[d + 3], gU[(d + 3) * KDIM + b], s3);
    }
    g_WU[a * KDIM + b] = __fadd_rn(__fadd_rn(s0, s1), __fadd_rn(s2, s3));
}

__device__ __forceinline__ float wrap_torus(float x) {
    const float PI_F     = 3.14159274101257324f;
    const float TWO_PI_F = 6.28318548202514648f;
    float t = __fadd_rn(x, PI_F);
    if (t >= TWO_PI_F) t = __fsub_rn(t, TWO_PI_F);
    if (t < 0.0f)      t = __fadd_rn(t, TWO_PI_F);
    return __fsub_rn(t, PI_F);
}

__device__ __forceinline__ void cp16(float* dst_smem, const float* src) {
    unsigned s = (unsigned)__cvta_generic_to_shared(dst_smem);
    asm volatile("cp.async.cg.shared.global [%0], [%1], 16;" :: "r"(s), "l"(src));
}
#define CP_COMMIT() asm volatile("cp.async.commit_group;")
#define CP_WAIT1()  asm volatile("cp.async.wait_group 1;")
#define CP_WAIT0()  asm volatile("cp.async.wait_group 0;")

__global__ __launch_bounds__(THREADS, 2)
void fr_kernel(const float* __restrict__ gx, const float* __restrict__ gv,
               const float* __restrict__ gf, const float* __restrict__ gU,
               const float* __restrict__ gW, const int* __restrict__ gsteps,
               float* __restrict__ gox, float* __restrict__ gov)
{
    extern __shared__ float smem[];
    float* sh    = smem;                 // h0 [32][64]                2048 f
    float* sfU   = sh   + 2048;          // fU [32][64]                2048 f
    float* kbuf  = sfU  + 2048;          // h2t 2x[64][H2TS]; epi stv+stx  4608 f
    float* sWU   = kbuf + 4608;          // [64][WUS]                  4224 f
    float* stage = sWU  + 4224;          // U 2x4096 ping / W 8192     8192 f
                                         // total 21120 f = 84,480 B -> 2 CTAs/SM

    const int tid  = threadIdx.x;
    const int wid  = tid >> 5;
    const int lane = tid & 31;
    const int row0 = blockIdx.x * CTA_M;

    auto issueU = [&](int c) {           // U rows [64c..64c+64) -> stage half
        float* dst = stage + (c & 1) * 4096;
        const float* src = gU + (size_t)c * 4096;
        #pragma unroll
        for (int i = 0; i < 2; ++i) { int idx = tid + i * THREADS; cp16(dst + idx * 4, src + idx * 4); }
        CP_COMMIT();
    };
    auto issueW = [&](int c) {           // W col-chunk c: [64 k][128 cols]
        const float* src = gW + c * 128;
        #pragma unroll
        for (int i = 0; i < 4; ++i) {
            int idx = tid + i * THREADS;
            int k = idx >> 5, seg = (idx & 31) * 4;
            cp16(stage + k * 128 + seg, src + (size_t)k * DDIM + seg);
        }
        CP_COMMIT();
    };

    issueU(0); issueU(1);
    #pragma unroll
    for (int i = 0; i < 8; ++i) {        // WU -> smem
        int idx = tid + i * THREADS;
        sWU[(idx >> 6) * WUS + (idx & 63)] = g_WU[idx];
    }
    __syncthreads();

    const int steps = gsteps ? gsteps[0] : 4;

    // ---- prologue: h0 = v@U, fU = f@U; warp = 8 rows x 16 k, thread 1r x 4k ----
    {
        const int prow = (wid >> 2) * 8 + (lane >> 2);        // 0..31
        const int pk   = (wid & 3) * 16 + (lane & 3) * 4;     // 0..60
        float4 ah = make_float4(0.f,0.f,0.f,0.f);
        float4 af = make_float4(0.f,0.f,0.f,0.f);
        #pragma unroll 1
        for (int c = 0; c < 8; ++c) {
            if (c < 7) { CP_WAIT1(); } else { CP_WAIT0(); }
            __syncthreads();
            const float* ub = stage + (c & 1) * 4096 + pk;
            const float* pv = gv + (size_t)(row0 + prow) * DDIM + c * 64;
            const float* pf = gf + (size_t)(row0 + prow) * DDIM + c * 64;
            #pragma unroll 4
            for (int d4 = 0; d4 < 16; ++d4) {
                float4 v4 = *(const float4*)(pv + d4 * 4);
                float4 f4 = *(const float4*)(pf + d4 * 4);
                #pragma unroll
                for (int dd = 0; dd < 4; ++dd) {
                    float vv = dd == 0 ? v4.x : dd == 1 ? v4.y : dd == 2 ? v4.z : v4.w;
                    float ff = dd == 0 ? f4.x : dd == 1 ? f4.y : dd == 2 ? f4.z : f4.w;
                    float4 u = *(const float4*)(ub + (d4 * 4 + dd) * KDIM);
                    ah.x = fmaf(vv, u.x, ah.x); ah.y = fmaf(vv, u.y, ah.y);
                    ah.z = fmaf(vv, u.z, ah.z); ah.w = fmaf(vv, u.w, ah.w);
                    af.x = fmaf(ff, u.x, af.x); af.y = fmaf(ff, u.y, af.y);
                    af.z = fmaf(ff, u.z, af.z); af.w = fmaf(ff, u.w, af.w);
                }
            }
            __syncthreads();
            if (c < 6) issueU(c + 2);
        }
        *(float4*)(sh  + prow * KDIM + pk) = ah;
        *(float4*)(sfU + prow * KDIM + pk) = af;
    }
    issueW(0);                            // epilogue chunk 0 rides through evals
    __syncthreads();

    // ---- eval ownership: warp = 8 rows x 16 cols, thread 2r x 2c ----
    const int erow = (wid >> 2) * 8 + (lane >> 3) * 2;        // even
    const int ecol = (wid & 3) * 16 + (lane & 7) * 2;         // even
    float4 h, fU;                         // {r,c},{r,c+1},{r+1,c},{r+1,c+1}
    {
        float2 a = *(const float2*)(sh + erow * KDIM + ecol);
        float2 b = *(const float2*)(sh + (erow + 1) * KDIM + ecol);
        h = make_float4(a.x, a.y, b.x, b.y);
        a = *(const float2*)(sfU + erow * KDIM + ecol);
        b = *(const float2*)(sfU + (erow + 1) * KDIM + ecol);
        fU = make_float4(a.x, a.y, b.x, b.y);
    }
    float4 Sv = make_float4(0.f, 0.f, 0.f, 0.f);
    float4 Sx = make_float4(0.f, 0.f, 0.f, 0.f);

    const double TH = 1.0 / (2.0 - cbrt(2.0));
    const float d1dtF = (float)(TH * 0.01);
    const float d2dtF = (float)((1.0 - 2.0 * TH) * 0.01);
    const float wv1 = (float)TH;
    const float wv2 = (float)(1.0 - 2.0 * TH);
    double Gam = 0.0;
    for (int s = 0; s < steps; ++s) {
        double R = (double)(steps - 1 - s);
        Gam += TH * (1.0 - 0.5 * TH + R) + (1.0 - 2.0 * TH) * (0.5 + R) + TH * (0.5 * TH + R);
    }

    int p = 0;
    auto evalstep = [&](float ddt, float wv, float wx) {
        float* h2b = kbuf + p * 2176;     // [64 kin][H2TS rows]
        float4 h2;
        h2.x = __fmul_rn(h.x, h.x); h2.y = __fmul_rn(h.y, h.y);
        h2.z = __fmul_rn(h.z, h.z); h2.w = __fmul_rn(h.w, h.w);
        *(float2*)(h2b + ecol * H2TS + erow)       = make_float2(h2.x, h2.z);
        *(float2*)(h2b + (ecol + 1) * H2TS + erow) = make_float2(h2.y, h2.w);
        __syncthreads();
        float4 out = make_float4(0.f, 0.f, 0.f, 0.f);
        const float* hr = h2b + erow;
        const float* wc = sWU + ecol;
        #pragma unroll 8
        for (int kin = 0; kin < KDIM; ++kin) {
            float2 hh = *(const float2*)(hr + kin * H2TS);
            float2 wu = *(const float2*)(wc + kin * WUS);
            out.x = fmaf(hh.x, wu.x, out.x);
            out.y = fmaf(hh.x, wu.y, out.y);
            out.z = fmaf(hh.y, wu.x, out.z);
            out.w = fmaf(hh.y, wu.y, out.w);
        }
        Sv.x = fmaf(wv, h2.x, Sv.x); Sv.y = fmaf(wv, h2.y, Sv.y);
        Sv.z = fmaf(wv, h2.z, Sv.z); Sv.w = fmaf(wv, h2.w, Sv.w);
        Sx.x = fmaf(wx, h2.x, Sx.x); Sx.y = fmaf(wx, h2.y, Sx.y);
        Sx.z = fmaf(wx, h2.z, Sx.z); Sx.w = fmaf(wx, h2.w, Sx.w);
        h.x = __fadd_rn(h.x, __fmul_rn(ddt, __fadd_rn(-out.x, fU.x)));
        h.y = __fadd_rn(h.y, __fmul_rn(ddt, __fadd_rn(-out.y, fU.y)));
        h.z = __fadd_rn(h.z, __fmul_rn(ddt, __fadd_rn(-out.z, fU.z)));
        h.w = __fadd_rn(h.w, __fmul_rn(ddt, __fadd_rn(-out.w, fU.w)));
        p ^= 1;
    };

    for (int s = 0; s < steps; ++s) {
        double R = (double)(steps - 1 - s);
        float wx1 = (float)(TH * (1.0 - 0.5 * TH + R));
        float wx2 = (float)((1.0 - 2.0 * TH) * (0.5 + R));
        float wx3 = (float)(TH * (0.5 * TH + R));
        evalstep(d1dtF, wv1, wx1);
        evalstep(d2dtF, wv2, wx2);
        evalstep(d1dtF, wv1, wx3);
    }

    // ---- epilogue: Gv=Sv@W, Gx=Sx@W; pass x 16r x 32c warp tiles ----
    __syncthreads();                      // all eval reads of kbuf done
    float* stv = kbuf;                    // [64 k][H2TS rows]
    float* stx = kbuf + 2176;
    *(float2*)(stv + ecol * H2TS + erow)       = make_float2(Sv.x, Sv.z);
    *(float2*)(stv + (ecol + 1) * H2TS + erow) = make_float2(Sv.y, Sv.w);
    *(float2*)(stx + ecol * H2TS + erow)       = make_float2(Sx.x, Sx.z);
    *(float2*)(stx + (ecol + 1) * H2TS + erow) = make_float2(Sx.y, Sx.w);

    const float dtF      = 0.01f;
    const float dt2F     = 1e-4f;
    const float stepsF   = (float)steps;
    const float stepsdtF = (float)((double)steps * 0.01);
    const float GamF     = (float)Gam;

    const int epass = wid >> 3;           // 0 = v-pass, 1 = x-pass
    const int row2  = ((wid >> 2) & 1) * 16 + (lane >> 2) * 2;   // even, 0..30
    const int cloc  = (wid & 3) * 32 + (lane & 3) * 8;           // 0..120

    #pragma unroll 1
    for (int P = 0; P < 4; ++P) {
        CP_WAIT0(); __syncthreads();      // W chunk P ready; S stores ordered (P==0)
        const float* sb = (epass ? stx : stv) + row2;
        const float* wb = stage + cloc;
        float4 A00 = make_float4(0.f,0.f,0.f,0.f), A01 = make_float4(0.f,0.f,0.f,0.f);
        float4 A10 = make_float4(0.f,0.f,0.f,0.f), A11 = make_float4(0.f,0.f,0.f,0.f);
        #pragma unroll 8
        for (int k = 0; k < KDIM; ++k) {
            float2 sq = *(const float2*)(sb + k * H2TS);
            float4 wA = *(const float4*)(wb + k * 128);
            float4 wB = *(const float4*)(wb + k * 128 + 4);
            A00.x = fmaf(sq.x, wA.x, A00.x); A00.y = fmaf(sq.x, wA.y, A00.y);
            A00.z = fmaf(sq.x, wA.z, A00.z); A00.w = fmaf(sq.x, wA.w, A00.w);
            A01.x = fmaf(sq.x, wB.x, A01.x); A01.y = fmaf(sq.x, wB.y, A01.y);
            A01.z = fmaf(sq.x, wB.z, A01.z); A01.w = fmaf(sq.x, wB.w, A01.w);
            A10.x = fmaf(sq.y, wA.x, A10.x); A10.y = fmaf(sq.y, wA.y, A10.y);
            A10.z = fmaf(sq.y, wA.z, A10.z); A10.w = fmaf(sq.y, wA.w, A10.w);
            A11.x = fmaf(sq.y, wB.x, A11.x); A11.y = fmaf(sq.y, wB.y, A11.y);
            A11.z = fmaf(sq.y, wB.z, A11.z); A11.w = fmaf(sq.y, wB.w, A11.w);
        }
        const int col = P * 128 + cloc;
        #pragma unroll
        for (int i = 0; i < 2; ++i) {
            const int r = row2 + i;
            const float4 GA = i ? A10 : A00;
            const float4 GB = i ? A11 : A01;
            const size_t off = (size_t)(row0 + r) * DDIM + col;
            float4 f0 = *(const float4*)(gf + off);
            float4 f1 = *(const float4*)(gf + off + 4);
            float4 va = *(const float4*)(gv + off);
            float4 vb = *(const float4*)(gv + off + 4);
            if (epass == 0) {             // v = v0 + dt*(-Gv + steps*f)
                float4 o0, o1;
                o0.x = __fadd_rn(va.x, __fmul_rn(dtF, __fadd_rn(-GA.x, __fmul_rn(stepsF, f0.x))));
                o0.y = __fadd_rn(va.y, __fmul_rn(dtF, __fadd_rn(-GA.y, __fmul_rn(stepsF, f0.y))));
                o0.z = __fadd_rn(va.z, __fmul_rn(dtF, __fadd_rn(-GA.z, __fmul_rn(stepsF, f0.z))));
                o0.w = __fadd_rn(va.w, __fmul_rn(dtF, __fadd_rn(-GA.w, __fmul_rn(stepsF, f0.w))));
                o1.x = __fadd_rn(vb.x, __fmul_rn(dtF, __fadd_rn(-GB.x, __fmul_rn(stepsF, f1.x))));
                o1.y = __fadd_rn(vb.y, __fmul_rn(dtF, __fadd_rn(-GB.y, __fmul_rn(stepsF, f1.y))));
                o1.z = __fadd_rn(vb.z, __fmul_rn(dtF, __fadd_rn(-GB.z, __fmul_rn(stepsF, f1.z))));
                o1.w = __fadd_rn(vb.w, __fmul_rn(dtF, __fadd_rn(-GB.w, __fmul_rn(stepsF, f1.w))));
                *(float4*)(gov + off)     = o0;
                *(float4*)(gov + off + 4) = o1;
            } else {                      // x = wrap(x0 + steps*dt*v0 + dt^2*(-Gx + Gam*f))
                float4 xa = *(const float4*)(gx + off);
                float4 xb = *(const float4*)(gx + off + 4);
                float4 o0, o1;
                o0.x = __fadd_rn(fmaf(stepsdtF, va.x, xa.x), __fmul_rn(dt2F, __fadd_rn(-GA.x, __fmul_rn(GamF, f0.x))));
                o0.y = __fadd_rn(fmaf(stepsdtF, va.y, xa.y), __fmul_rn(dt2F, __fadd_rn(-GA.y, __fmul_rn(GamF, f0.y))));
                o0.z = __fadd_rn(fmaf(stepsdtF, va.z, xa.z), __fmul_rn(dt2F, __fadd_rn(-GA.z, __fmul_rn(GamF, f0.z))));
                o0.w = __fadd_rn(fmaf(stepsdtF, va.w, xa.w), __fmul_rn(dt2F, __fadd_rn(-GA.w, __fmul_rn(GamF, f0.w))));
                o1.x = __fadd_rn(fmaf(stepsdtF, vb.x, xb.x), __fmul_rn(dt2F, __fadd_rn(-GB.x, __fmul_rn(GamF, f1.x))));
                o1.y = __fadd_rn(fmaf(stepsdtF, vb.y, xb.y), __fmul_rn(dt2F, __fadd_rn(-GB.y, __fmul_rn(GamF, f1.y))));
                o1.z = __fadd_rn(fmaf(stepsdtF, vb.z, xb.z), __fmul_rn(dt2F, __fadd_rn(-GB.z, __fmul_rn(GamF, f1.z))));
                o1.w = __fadd_rn(fmaf(stepsdtF, vb.w, xb.w), __fmul_rn(dt2F, __fadd_rn(-GB.w, __fmul_rn(GamF, f1.w))));
                if (steps != 0) {
                    o0.x = wrap_torus(o0.x); o0.y = wrap_torus(o0.y);
                    o0.z = wrap_torus(o0.z); o0.w = wrap_torus(o0.w);
                    o1.x = wrap_torus(o1.x); o1.y = wrap_torus(o1.y);
                    o1.z = wrap_torus(o1.z); o1.w = wrap_torus(o1.w);
                }
                *(float4*)(gox + off)     = o0;
                *(float4*)(gox + off + 4) = o1;
            }
        }
        __syncthreads();                  // chunk fully consumed
        if (P < 3) issueW(P + 1);
    }
    CP_WAIT0();
}

extern "C" void kernel_launch(void* const* d_in, const int* in_sizes, int n_in,
                              void* d_out, int out_size)
{
    const float* x = (const float*)d_in[0];
    const float* v = (const float*)d_in[1];
    const float* f = (const float*)d_in[2];
    const float* U = (const float*)d_in[3];
    const float* W = (const float*)d_in[4];
    const int* steps = (n_in >= 6) ? (const int*)d_in[5] : nullptr;

    const int B  = in_sizes[0] / DDIM;
    const int BD = B * DDIM;
    float* ox = (float*)d_out;
    float* ov = ox + BD;

    wu_kernel<<<KDIM, KDIM>>>(W, U);

    const int smem_floats = 2048 + 2048 + 4608 + 4224 + 8192;  // 21120
    const int smem_bytes = smem_floats * 4;                    // 84,480 B
    cudaFuncSetAttribute(fr_kernel, cudaFuncAttributeMaxDynamicSharedMemorySize, smem_bytes);
    fr_kernel<<<B / CTA_M, THREADS, smem_bytes>>>(x, v, f, U, W, steps, ox, ov);
}

// round 16
// speedup vs baseline: 1.4601x; 1.2017x over previous
#include <cuda_runtime.h>
#include <math.h>

// ForestRuthIntegrator v8 — v7 + cp.async-staged prologue v/f (coalesced).
// Fixes the 8-wavefront-per-LDG dedup waste of direct gv/gf reads.
// All per-element accumulation orders bitwise == v7.

#define THREADS 512
#define CTA_M   32
#define DDIM    512
#define KDIM    64
#define WUS     66      // WU row stride (even, float2-aligned)
#define H2TS    34      // transposed h^2 / S stride (even)
#define VFS     36      // staged v/f row stride (bank-quad spread)

__device__ float g_WU[KDIM * KDIM];

__global__ void wu_kernel(const float* __restrict__ gW, const float* __restrict__ gU) {
    const int a = blockIdx.x, b = threadIdx.x;
    const float* wr = gW + a * DDIM;
    float s0 = 0.f, s1 = 0.f, s2 = 0.f, s3 = 0.f;
    #pragma unroll 4
    for (int d = 0; d < DDIM; d += 4) {
        s0 = fmaf(wr[d + 0], gU[(d + 0) * KDIM + b], s0);
        s1 = fmaf(wr[d + 1], gU[(d + 1) * KDIM + b], s1);
        s2 = fmaf(wr[d + 2], gU[(d + 2) * KDIM + b], s2);
        s3 = fmaf(wr[d + 3], gU[(d + 3) * KDIM + b], s3);
    }
    g_WU[a * KDIM + b] = __fadd_rn(__fadd_rn(s0, s1), __fadd_rn(s2, s3));
}

__device__ __forceinline__ float wrap_torus(float x) {
    const float PI_F     = 3.14159274101257324f;
    const float TWO_PI_F = 6.28318548202514648f;
    float t = __fadd_rn(x, PI_F);
    if (t >= TWO_PI_F) t = __fsub_rn(t, TWO_PI_F);
    if (t < 0.0f)      t = __fadd_rn(t, TWO_PI_F);
    return __fsub_rn(t, PI_F);
}

__device__ __forceinline__ void cp16(float* dst_smem, const float* src) {
    unsigned s = (unsigned)__cvta_generic_to_shared(dst_smem);
    asm volatile("cp.async.cg.shared.global [%0], [%1], 16;" :: "r"(s), "l"(src));
}
#define CP_COMMIT() asm volatile("cp.async.commit_group;")
#define CP_WAIT1()  asm volatile("cp.async.wait_group 1;")
#define CP_WAIT0()  asm volatile("cp.async.wait_group 0;")

__global__ __launch_bounds__(THREADS, 2)
void fr_kernel(const float* __restrict__ gx, const float* __restrict__ gv,
               const float* __restrict__ gf, const float* __restrict__ gU,
               const float* __restrict__ gW, const int* __restrict__ gsteps,
               float* __restrict__ gox, float* __restrict__ gov)
{
    extern __shared__ float smem[];
    float* sh    = smem;                 // h0 [32][64]                2048 f
    float* sfU   = sh   + 2048;          // fU [32][64]                2048 f
    float* kbuf  = sfU  + 2048;          // h2t 2x[64][H2TS]; epi stv+stx  4608 f
    float* sWU   = kbuf + 4608;          // [64][WUS]                  4224 f
    float* stage = sWU  + 4224;          // prologue U 2x2048 + vf 2x2304; epi W 8192
                                         // stage = 8704 f; total 21632 f = 86,528 B

    const int tid  = threadIdx.x;
    const int wid  = tid >> 5;
    const int lane = tid & 31;
    const int row0 = blockIdx.x * CTA_M;

    // prologue chunk c (32 d-rows): U [32][64] + v [32][VFS] + f [32][VFS]
    auto issueUVF = [&](int c) {
        const int half = c & 1;
        float* du = stage + half * 2048;
        float* dv = stage + 4096 + half * 2304;
        {   // U rows 32c..32c+31, coalesced 256B/row
            int d = tid >> 4, seg = (tid & 15) * 4;
            cp16(du + d * KDIM + seg, gU + (size_t)(c * 32 + d) * KDIM + seg);
        }
        {   // v (tid<256) / f (tid>=256): 128B per row, coalesced
            int r = (tid >> 3) & 31;
            int seg = (tid & 7) * 4;
            if (tid < 256)
                cp16(dv + r * VFS + seg, gv + (size_t)(row0 + r) * DDIM + c * 32 + seg);
            else
                cp16(dv + 1152 + r * VFS + seg, gf + (size_t)(row0 + r) * DDIM + c * 32 + seg);
        }
        CP_COMMIT();
    };
    auto issueW = [&](int c) {           // W col-chunk c: [64 k][128 cols]
        const float* src = gW + c * 128;
        #pragma unroll
        for (int i = 0; i < 4; ++i) {
            int idx = tid + i * THREADS;
            int k = idx >> 5, seg = (idx & 31) * 4;
            cp16(stage + k * 128 + seg, src + (size_t)k * DDIM + seg);
        }
        CP_COMMIT();
    };

    issueUVF(0); issueUVF(1);
    #pragma unroll
    for (int i = 0; i < 8; ++i) {        // WU -> smem
        int idx = tid + i * THREADS;
        sWU[(idx >> 6) * WUS + (idx & 63)] = g_WU[idx];
    }
    __syncthreads();

    const int steps = gsteps ? gsteps[0] : 4;

    // ---- prologue: h0 = v@U, fU = f@U; warp = 8 rows x 16 k, thread 1r x 4k ----
    {
        const int prow = (wid >> 2) * 8 + (lane >> 2);        // 0..31
        const int pk   = (wid & 3) * 16 + (lane & 3) * 4;     // 0..60
        float4 ah = make_float4(0.f,0.f,0.f,0.f);
        float4 af = make_float4(0.f,0.f,0.f,0.f);
        #pragma unroll 1
        for (int c = 0; c < 16; ++c) {
            if (c < 15) { CP_WAIT1(); } else { CP_WAIT0(); }
            __syncthreads();
            const float* ub = stage + (c & 1) * 2048 + pk;
            const float* pv = stage + 4096 + (c & 1) * 2304 + prow * VFS;
            const float* pf = pv + 1152;
            #pragma unroll 4
            for (int d4 = 0; d4 < 8; ++d4) {
                float4 v4 = *(const float4*)(pv + d4 * 4);
                float4 f4 = *(const float4*)(pf + d4 * 4);
                #pragma unroll
                for (int dd = 0; dd < 4; ++dd) {
                    float vv = dd == 0 ? v4.x : dd == 1 ? v4.y : dd == 2 ? v4.z : v4.w;
                    float ff = dd == 0 ? f4.x : dd == 1 ? f4.y : dd == 2 ? f4.z : f4.w;
                    float4 u = *(const float4*)(ub + (d4 * 4 + dd) * KDIM);
                    ah.x = fmaf(vv, u.x, ah.x); ah.y = fmaf(vv, u.y, ah.y);
                    ah.z = fmaf(vv, u.z, ah.z); ah.w = fmaf(vv, u.w, ah.w);
                    af.x = fmaf(ff, u.x, af.x); af.y = fmaf(ff, u.y, af.y);
                    af.z = fmaf(ff, u.z, af.z); af.w = fmaf(ff, u.w, af.w);
                }
            }
            __syncthreads();
            if (c < 14) issueUVF(c + 2);
        }
        *(float4*)(sh  + prow * KDIM + pk) = ah;
        *(float4*)(sfU + prow * KDIM + pk) = af;
    }
    issueW(0);                            // epilogue chunk 0 rides through evals
    __syncthreads();

    // ---- eval ownership: warp = 8 rows x 16 cols, thread 2r x 2c ----
    const int erow = (wid >> 2) * 8 + (lane >> 3) * 2;        // even
    const int ecol = (wid & 3) * 16 + (lane & 7) * 2;         // even
    float4 h, fU;                         // {r,c},{r,c+1},{r+1,c},{r+1,c+1}
    {
        float2 a = *(const float2*)(sh + erow * KDIM + ecol);
        float2 b = *(const float2*)(sh + (erow + 1) * KDIM + ecol);
        h = make_float4(a.x, a.y, b.x, b.y);
        a = *(const float2*)(sfU + erow * KDIM + ecol);
        b = *(const float2*)(sfU + (erow + 1) * KDIM + ecol);
        fU = make_float4(a.x, a.y, b.x, b.y);
    }
    float4 Sv = make_float4(0.f, 0.f, 0.f, 0.f);
    float4 Sx = make_float4(0.f, 0.f, 0.f, 0.f);

    const double TH = 1.0 / (2.0 - cbrt(2.0));
    const float d1dtF = (float)(TH * 0.01);
    const float d2dtF = (float)((1.0 - 2.0 * TH) * 0.01);
    const float wv1 = (float)TH;
    const float wv2 = (float)(1.0 - 2.0 * TH);
    double Gam = 0.0;
    for (int s = 0; s < steps; ++s) {
        double R = (double)(steps - 1 - s);
        Gam += TH * (1.0 - 0.5 * TH + R) + (1.0 - 2.0 * TH) * (0.5 + R) + TH * (0.5 * TH + R);
    }

    int p = 0;
    auto evalstep = [&](float ddt, float wv, float wx) {
        float* h2b = kbuf + p * 2176;     // [64 kin][H2TS rows]
        float4 h2;
        h2.x = __fmul_rn(h.x, h.x); h2.y = __fmul_rn(h.y, h.y);
        h2.z = __fmul_rn(h.z, h.z); h2.w = __fmul_rn(h.w, h.w);
        *(float2*)(h2b + ecol * H2TS + erow)       = make_float2(h2.x, h2.z);
        *(float2*)(h2b + (ecol + 1) * H2TS + erow) = make_float2(h2.y, h2.w);
        __syncthreads();
        float4 out = make_float4(0.f, 0.f, 0.f, 0.f);
        const float* hr = h2b + erow;
        const float* wc = sWU + ecol;
        #pragma unroll 8
        for (int kin = 0; kin < KDIM; ++kin) {
            float2 hh = *(const float2*)(hr + kin * H2TS);
            float2 wu = *(const float2*)(wc + kin * WUS);
            out.x = fmaf(hh.x, wu.x, out.x);
            out.y = fmaf(hh.x, wu.y, out.y);
            out.z = fmaf(hh.y, wu.x, out.z);
            out.w = fmaf(hh.y, wu.y, out.w);
        }
        Sv.x = fmaf(wv, h2.x, Sv.x); Sv.y = fmaf(wv, h2.y, Sv.y);
        Sv.z = fmaf(wv, h2.z, Sv.z); Sv.w = fmaf(wv, h2.w, Sv.w);
        Sx.x = fmaf(wx, h2.x, Sx.x); Sx.y = fmaf(wx, h2.y, Sx.y);
        Sx.z = fmaf(wx, h2.z, Sx.z); Sx.w = fmaf(wx, h2.w, Sx.w);
        h.x = __fadd_rn(h.x, __fmul_rn(ddt, __fadd_rn(-out.x, fU.x)));
        h.y = __fadd_rn(h.y, __fmul_rn(ddt, __fadd_rn(-out.y, fU.y)));
        h.z = __fadd_rn(h.z, __fmul_rn(ddt, __fadd_rn(-out.z, fU.z)));
        h.w = __fadd_rn(h.w, __fmul_rn(ddt, __fadd_rn(-out.w, fU.w)));
        p ^= 1;
    };

    for (int s = 0; s < steps; ++s) {
        double R = (double)(steps - 1 - s);
        float wx1 = (float)(TH * (1.0 - 0.5 * TH + R));
        float wx2 = (float)((1.0 - 2.0 * TH) * (0.5 + R));
        float wx3 = (float)(TH * (0.5 * TH + R));
        evalstep(d1dtF, wv1, wx1);
        evalstep(d2dtF, wv2, wx2);
        evalstep(d1dtF, wv1, wx3);
    }

    // ---- epilogue: Gv=Sv@W, Gx=Sx@W; pass x 16r x 32c warp tiles ----
    __syncthreads();                      // all eval reads of kbuf done
    float* stv = kbuf;                    // [64 k][H2TS rows]
    float* stx = kbuf + 2176;
    *(float2*)(stv + ecol * H2TS + erow)       = make_float2(Sv.x, Sv.z);
    *(float2*)(stv + (ecol + 1) * H2TS + erow) = make_float2(Sv.y, Sv.w);
    *(float2*)(stx + ecol * H2TS + erow)       = make_float2(Sx.x, Sx.z);
    *(float2*)(stx + (ecol + 1) * H2TS + erow) = make_float2(Sx.y, Sx.w);

    const float dtF      = 0.01f;
    const float dt2F     = 1e-4f;
    const float stepsF   = (float)steps;
    const float stepsdtF = (float)((double)steps * 0.01);
    const float GamF     = (float)Gam;

    const int epass = wid >> 3;           // 0 = v-pass, 1 = x-pass
    const int row2  = ((wid >> 2) & 1) * 16 + (lane >> 2) * 2;   // even, 0..30
    const int cloc  = (wid & 3) * 32 + (lane & 3) * 8;           // 0..120

    #pragma unroll 1
    for (int P = 0; P < 4; ++P) {
        CP_WAIT0(); __syncthreads();      // W chunk P ready; S stores ordered (P==0)
        const float* sb = (epass ? stx : stv) + row2;
        const float* wb = stage + cloc;
        float4 A00 = make_float4(0.f,0.f,0.f,0.f), A01 = make_float4(0.f,0.f,0.f,0.f);
        float4 A10 = make_float4(0.f,0.f,0.f,0.f), A11 = make_float4(0.f,0.f,0.f,0.f);
        #pragma unroll 8
        for (int k = 0; k < KDIM; ++k) {
            float2 sq = *(const float2*)(sb + k * H2TS);
            float4 wA = *(const float4*)(wb + k * 128);
            float4 wB = *(const float4*)(wb + k * 128 + 4);
            A00.x = fmaf(sq.x, wA.x, A00.x); A00.y = fmaf(sq.x, wA.y, A00.y);
            A00.z = fmaf(sq.x, wA.z, A00.z); A00.w = fmaf(sq.x, wA.w, A00.w);
            A01.x = fmaf(sq.x, wB.x, A01.x); A01.y = fmaf(sq.x, wB.y, A01.y);
            A01.z = fmaf(sq.x, wB.z, A01.z); A01.w = fmaf(sq.x, wB.w, A01.w);
            A10.x = fmaf(sq.y, wA.x, A10.x); A10.y = fmaf(sq.y, wA.y, A10.y);
            A10.z = fmaf(sq.y, wA.z, A10.z); A10.w = fmaf(sq.y, wA.w, A10.w);
            A11.x = fmaf(sq.y, wB.x, A11.x); A11.y = fmaf(sq.y, wB.y, A11.y);
            A11.z = fmaf(sq.y, wB.z, A11.z); A11.w = fmaf(sq.y, wB.w, A11.w);
        }
        const int col = P * 128 + cloc;
        #pragma unroll
        for (int i = 0; i < 2; ++i) {
            const int r = row2 + i;
            const float4 GA = i ? A10 : A00;
            const float4 GB = i ? A11 : A01;
            const size_t off = (size_t)(row0 + r) * DDIM + col;
            float4 f0 = *(const float4*)(gf + off);
            float4 f1 = *(const float4*)(gf + off + 4);
            float4 va = *(const float4*)(gv + off);
            float4 vb = *(const float4*)(gv + off + 4);
            if (epass == 0) {             // v = v0 + dt*(-Gv + steps*f)
                float4 o0, o1;
                o0.x = __fadd_rn(va.x, __fmul_rn(dtF, __fadd_rn(-GA.x, __fmul_rn(stepsF, f0.x))));
                o0.y = __fadd_rn(va.y, __fmul_rn(dtF, __fadd_rn(-GA.y, __fmul_rn(stepsF, f0.y))));
                o0.z = __fadd_rn(va.z, __fmul_rn(dtF, __fadd_rn(-GA.z, __fmul_rn(stepsF, f0.z))));
                o0.w = __fadd_rn(va.w, __fmul_rn(dtF, __fadd_rn(-GA.w, __fmul_rn(stepsF, f0.w))));
                o1.x = __fadd_rn(vb.x, __fmul_rn(dtF, __fadd_rn(-GB.x, __fmul_rn(stepsF, f1.x))));
                o1.y = __fadd_rn(vb.y, __fmul_rn(dtF, __fadd_rn(-GB.y, __fmul_rn(stepsF, f1.y))));
                o1.z = __fadd_rn(vb.z, __fmul_rn(dtF, __fadd_rn(-GB.z, __fmul_rn(stepsF, f1.z))));
                o1.w = __fadd_rn(vb.w, __fmul_rn(dtF, __fadd_rn(-GB.w, __fmul_rn(stepsF, f1.w))));
                *(float4*)(gov + off)     = o0;
                *(float4*)(gov + off + 4) = o1;
            } else {                      // x = wrap(x0 + steps*dt*v0 + dt^2*(-Gx + Gam*f))
                float4 xa = *(const float4*)(gx + off);
                float4 xb = *(const float4*)(gx + off + 4);
                float4 o0, o1;
                o0.x = __fadd_rn(fmaf(stepsdtF, va.x, xa.x), __fmul_rn(dt2F, __fadd_rn(-GA.x, __fmul_rn(GamF, f0.x))));
                o0.y = __fadd_rn(fmaf(stepsdtF, va.y, xa.y), __fmul_rn(dt2F, __fadd_rn(-GA.y, __fmul_rn(GamF, f0.y))));
                o0.z = __fadd_rn(fmaf(stepsdtF, va.z, xa.z), __fmul_rn(dt2F, __fadd_rn(-GA.z, __fmul_rn(GamF, f0.z))));
                o0.w = __fadd_rn(fmaf(stepsdtF, va.w, xa.w), __fmul_rn(dt2F, __fadd_rn(-GA.w, __fmul_rn(GamF, f0.w))));
                o1.x = __fadd_rn(fmaf(stepsdtF, vb.x, xb.x), __fmul_rn(dt2F, __fadd_rn(-GB.x, __fmul_rn(GamF, f1.x))));
                o1.y = __fadd_rn(fmaf(stepsdtF, vb.y, xb.y), __fmul_rn(dt2F, __fadd_rn(-GB.y, __fmul_rn(GamF, f1.y))));
                o1.z = __fadd_rn(fmaf(stepsdtF, vb.z, xb.z), __fmul_rn(dt2F, __fadd_rn(-GB.z, __fmul_rn(GamF, f1.z))));
                o1.w = __fadd_rn(fmaf(stepsdtF, vb.w, xb.w), __fmul_rn(dt2F, __fadd_rn(-GB.w, __fmul_rn(GamF, f1.w))));
                if (steps != 0) {
                    o0.x = wrap_torus(o0.x); o0.y = wrap_torus(o0.y);
                    o0.z = wrap_torus(o0.z); o0.w = wrap_torus(o0.w);
                    o1.x = wrap_torus(o1.x); o1.y = wrap_torus(o1.y);
                    o1.z = wrap_torus(o1.z); o1.w = wrap_torus(o1.w);
                }
                *(float4*)(gox + off)     = o0;
                *(float4*)(gox + off + 4) = o1;
            }
        }
        __syncthreads();                  // chunk fully consumed
        if (P < 3) issueW(P + 1);
    }
    CP_WAIT0();
}

extern "C" void kernel_launch(void* const* d_in, const int* in_sizes, int n_in,
                              void* d_out, int out_size)
{
    const float* x = (const float*)d_in[0];
    const float* v = (const float*)d_in[1];
    const float* f = (const float*)d_in[2];
    const float* U = (const float*)d_in[3];
    const float* W = (const float*)d_in[4];
    const int* steps = (n_in >= 6) ? (const int*)d_in[5] : nullptr;

    const int B  = in_sizes[0] / DDIM;
    const int BD = B * DDIM;
    float* ox = (float*)d_out;
    float* ov = ox + BD;

    wu_kernel<<<KDIM, KDIM>>>(W, U);

    const int smem_floats = 2048 + 2048 + 4608 + 4224 + 8704;  // 21632
    const int smem_bytes = smem_floats * 4;                    // 86,528 B
    cudaFuncSetAttribute(fr_kernel, cudaFuncAttributeMaxDynamicSharedMemorySize, smem_bytes);
    fr_kernel<<<B / CTA_M, THREADS, smem_bytes>>>(x, v, f, U, W, steps, ox, ov);
}

// round 17
// speedup vs baseline: 1.6495x; 1.1297x over previous
#include <cuda_runtime.h>
#include <math.h>

// ForestRuthIntegrator v9 — CTA_M=64 coarsening. 512 thr, occ 2, grid 512.
// Thread owns 2r x 4k K-state in REGISTERS end-to-end (no sh/sfU smem).
// Prologue 2r x 4k, eval 2r x 4c, epilogue 8r x 4c tiles: B-operand smem
// reads amortized over 2x FMAs. Per-element accumulation orders bitwise == v8.

#define THREADS 512
#define CTA_M   64
#define DDIM    512
#define KDIM    64
#define WUS     68      // sWU / h2t / S stride (mult of 4 for float4 reads)
#define VFS     36      // staged v/f row stride

__device__ float g_WU[KDIM * KDIM];

__global__ void wu_kernel(const float* __restrict__ gW, const float* __restrict__ gU) {
    const int a = blockIdx.x, b = threadIdx.x;
    const float* wr = gW + a * DDIM;
    float s0 = 0.f, s1 = 0.f, s2 = 0.f, s3 = 0.f;
    #pragma unroll 4
    for (int d = 0; d < DDIM; d += 4) {
        s0 = fmaf(wr[d + 0], gU[(d + 0) * KDIM + b], s0);
        s1 = fmaf(wr[d + 1], gU[(d + 1) * KDIM + b], s1);
        s2 = fmaf(wr[d + 2], gU[(d + 2) * KDIM + b], s2);
        s3 = fmaf(wr[d + 3], gU[(d + 3) * KDIM + b], s3);
    }
    g_WU[a * KDIM + b] = __fadd_rn(__fadd_rn(s0, s1), __fadd_rn(s2, s3));
}

__device__ __forceinline__ float wrap_torus(float x) {
    const float PI_F     = 3.14159274101257324f;
    const float TWO_PI_F = 6.28318548202514648f;
    float t = __fadd_rn(x, PI_F);
    if (t >= TWO_PI_F) t = __fsub_rn(t, TWO_PI_F);
    if (t < 0.0f)      t = __fadd_rn(t, TWO_PI_F);
    return __fsub_rn(t, PI_F);
}

__device__ __forceinline__ void cp16(float* dst_smem, const float* src) {
    unsigned s = (unsigned)__cvta_generic_to_shared(dst_smem);
    asm volatile("cp.async.cg.shared.global [%0], [%1], 16;" :: "r"(s), "l"(src));
}
#define CP_COMMIT() asm volatile("cp.async.commit_group;")
#define CP_WAIT1()  asm volatile("cp.async.wait_group 1;")
#define CP_WAIT0()  asm volatile("cp.async.wait_group 0;")

__global__ __launch_bounds__(THREADS, 2)
void fr_kernel(const float* __restrict__ gx, const float* __restrict__ gv,
               const float* __restrict__ gf, const float* __restrict__ gU,
               const float* __restrict__ gW, const int* __restrict__ gsteps,
               float* __restrict__ gox, float* __restrict__ gov)
{
    extern __shared__ float smem[];
    float* kbuf  = smem;                 // h2t 2x[64][WUS]=8704; epi stv+stx alias
    float* sWU   = kbuf + 8704;          // [64][WUS]  4352 f
    float* stage = sWU  + 4352;          // prologue U 2x2048 + vf 2x4608 = 13312;
                                         // epilogue W 8192 aliases. total 26368 f = 105,472 B

    const int tid  = threadIdx.x;
    const int wid  = tid >> 5;
    const int lane = tid & 31;
    const int row0 = blockIdx.x * CTA_M;
    const int trow = (tid >> 4) * 2;     // rows trow, trow+1 (0..62)
    const int tcol = (tid & 15) * 4;     // k/cols tcol..tcol+3

    // prologue chunk c (32 d): U [32][64] + v [64][VFS] + f [64][VFS]
    auto issueUVF = [&](int c) {
        float* du = stage + (c & 1) * 2048;
        float* dv = stage + 4096 + (c & 1) * 4608;
        {   int d = tid >> 4, seg = (tid & 15) * 4;
            cp16(du + d * KDIM + seg, gU + (size_t)(c * 32 + d) * KDIM + seg); }
        {   int r = tid >> 3, seg = (tid & 7) * 4;
            cp16(dv + r * VFS + seg,        gv + (size_t)(row0 + r) * DDIM + c * 32 + seg);
            cp16(dv + 2304 + r * VFS + seg, gf + (size_t)(row0 + r) * DDIM + c * 32 + seg); }
        CP_COMMIT();
    };
    auto issueW = [&](int c) {           // W col-chunk c: [64 k][128 cols]
        const float* src = gW + c * 128;
        #pragma unroll
        for (int i = 0; i < 4; ++i) {
            int idx = tid + i * THREADS;
            int k = idx >> 5, seg = (idx & 31) * 4;
            cp16(stage + k * 128 + seg, src + (size_t)k * DDIM + seg);
        }
        CP_COMMIT();
    };

    issueUVF(0); issueUVF(1);
    #pragma unroll
    for (int i = 0; i < 8; ++i) {        // WU -> smem
        int idx = tid + i * THREADS;
        sWU[(idx >> 6) * WUS + (idx & 63)] = g_WU[idx];
    }
    __syncthreads();

    const int steps = gsteps ? gsteps[0] : 4;

    // ---- prologue: h0 = v@U, fU = f@U ; thread 2r x 4k, all in registers ----
    float4 hA  = make_float4(0.f,0.f,0.f,0.f), hB  = make_float4(0.f,0.f,0.f,0.f);
    float4 fUA = make_float4(0.f,0.f,0.f,0.f), fUB = make_float4(0.f,0.f,0.f,0.f);
    #pragma unroll 1
    for (int c = 0; c < 16; ++c) {
        if (c < 15) { CP_WAIT1(); } else { CP_WAIT0(); }
        __syncthreads();
        const float* ub  = stage + (c & 1) * 2048 + tcol;
        const float* pv0 = stage + 4096 + (c & 1) * 4608 + trow * VFS;
        const float* pv1 = pv0 + VFS;
        const float* pf0 = pv0 + 2304;
        const float* pf1 = pf0 + VFS;
        #pragma unroll 4
        for (int d4 = 0; d4 < 8; ++d4) {
            float4 v0 = *(const float4*)(pv0 + d4 * 4);
            float4 v1 = *(const float4*)(pv1 + d4 * 4);
            float4 f0 = *(const float4*)(pf0 + d4 * 4);
            float4 f1 = *(const float4*)(pf1 + d4 * 4);
            #pragma unroll
            for (int dd = 0; dd < 4; ++dd) {
                float vv0 = dd == 0 ? v0.x : dd == 1 ? v0.y : dd == 2 ? v0.z : v0.w;
                float vv1 = dd == 0 ? v1.x : dd == 1 ? v1.y : dd == 2 ? v1.z : v1.w;
                float ff0 = dd == 0 ? f0.x : dd == 1 ? f0.y : dd == 2 ? f0.z : f0.w;
                float ff1 = dd == 0 ? f1.x : dd == 1 ? f1.y : dd == 2 ? f1.z : f1.w;
                float4 u = *(const float4*)(ub + (d4 * 4 + dd) * KDIM);
                hA.x  = fmaf(vv0, u.x, hA.x);  hA.y  = fmaf(vv0, u.y, hA.y);
                hA.z  = fmaf(vv0, u.z, hA.z);  hA.w  = fmaf(vv0, u.w, hA.w);
                hB.x  = fmaf(vv1, u.x, hB.x);  hB.y  = fmaf(vv1, u.y, hB.y);
                hB.z  = fmaf(vv1, u.z, hB.z);  hB.w  = fmaf(vv1, u.w, hB.w);
                fUA.x = fmaf(ff0, u.x, fUA.x); fUA.y = fmaf(ff0, u.y, fUA.y);
                fUA.z = fmaf(ff0, u.z, fUA.z); fUA.w = fmaf(ff0, u.w, fUA.w);
                fUB.x = fmaf(ff1, u.x, fUB.x); fUB.y = fmaf(ff1, u.y, fUB.y);
                fUB.z = fmaf(ff1, u.z, fUB.z); fUB.w = fmaf(ff1, u.w, fUB.w);
            }
        }
        __syncthreads();
        if (c < 14) issueUVF(c + 2);
    }
    issueW(0);                            // epilogue chunk 0 rides through evals

    float4 SvA = make_float4(0.f,0.f,0.f,0.f), SvB = make_float4(0.f,0.f,0.f,0.f);
    float4 SxA = make_float4(0.f,0.f,0.f,0.f), SxB = make_float4(0.f,0.f,0.f,0.f);

    const double TH = 1.0 / (2.0 - cbrt(2.0));
    const float d1dtF = (float)(TH * 0.01);
    const float d2dtF = (float)((1.0 - 2.0 * TH) * 0.01);
    const float wv1 = (float)TH;
    const float wv2 = (float)(1.0 - 2.0 * TH);
    double Gam = 0.0;
    for (int s = 0; s < steps; ++s) {
        double R = (double)(steps - 1 - s);
        Gam += TH * (1.0 - 0.5 * TH + R) + (1.0 - 2.0 * TH) * (0.5 + R) + TH * (0.5 * TH + R);
    }

    int p = 0;
    auto evalstep = [&](float ddt, float wv, float wx) {
        float* h2b = kbuf + p * 4352;     // [64 kin][WUS rows]
        float4 h2A, h2B;
        h2A.x = __fmul_rn(hA.x, hA.x); h2A.y = __fmul_rn(hA.y, hA.y);
        h2A.z = __fmul_rn(hA.z, hA.z); h2A.w = __fmul_rn(hA.w, hA.w);
        h2B.x = __fmul_rn(hB.x, hB.x); h2B.y = __fmul_rn(hB.y, hB.y);
        h2B.z = __fmul_rn(hB.z, hB.z); h2B.w = __fmul_rn(hB.w, hB.w);
        *(float2*)(h2b + (tcol + 0) * WUS + trow) = make_float2(h2A.x, h2B.x);
        *(float2*)(h2b + (tcol + 1) * WUS + trow) = make_float2(h2A.y, h2B.y);
        *(float2*)(h2b + (tcol + 2) * WUS + trow) = make_float2(h2A.z, h2B.z);
        *(float2*)(h2b + (tcol + 3) * WUS + trow) = make_float2(h2A.w, h2B.w);
        __syncthreads();
        float4 outA = make_float4(0.f,0.f,0.f,0.f), outB = make_float4(0.f,0.f,0.f,0.f);
        const float* hr = h2b + trow;
        const float* wc = sWU + tcol;
        #pragma unroll 8
        for (int kin = 0; kin < KDIM; ++kin) {
            float2 hh = *(const float2*)(hr + kin * WUS);
            float4 wu = *(const float4*)(wc + kin * WUS);
            outA.x = fmaf(hh.x, wu.x, outA.x); outA.y = fmaf(hh.x, wu.y, outA.y);
            outA.z = fmaf(hh.x, wu.z, outA.z); outA.w = fmaf(hh.x, wu.w, outA.w);
            outB.x = fmaf(hh.y, wu.x, outB.x); outB.y = fmaf(hh.y, wu.y, outB.y);
            outB.z = fmaf(hh.y, wu.z, outB.z); outB.w = fmaf(hh.y, wu.w, outB.w);
        }
        SvA.x = fmaf(wv, h2A.x, SvA.x); SvA.y = fmaf(wv, h2A.y, SvA.y);
        SvA.z = fmaf(wv, h2A.z, SvA.z); SvA.w = fmaf(wv, h2A.w, SvA.w);
        SvB.x = fmaf(wv, h2B.x, SvB.x); SvB.y = fmaf(wv, h2B.y, SvB.y);
        SvB.z = fmaf(wv, h2B.z, SvB.z); SvB.w = fmaf(wv, h2B.w, SvB.w);
        SxA.x = fmaf(wx, h2A.x, SxA.x); SxA.y = fmaf(wx, h2A.y, SxA.y);
        SxA.z = fmaf(wx, h2A.z, SxA.z); SxA.w = fmaf(wx, h2A.w, SxA.w);
        SxB.x = fmaf(wx, h2B.x, SxB.x); SxB.y = fmaf(wx, h2B.y, SxB.y);
        SxB.z = fmaf(wx, h2B.z, SxB.z); SxB.w = fmaf(wx, h2B.w, SxB.w);
        hA.x = __fadd_rn(hA.x, __fmul_rn(ddt, __fadd_rn(-outA.x, fUA.x)));
        hA.y = __fadd_rn(hA.y, __fmul_rn(ddt, __fadd_rn(-outA.y, fUA.y)));
        hA.z = __fadd_rn(hA.z, __fmul_rn(ddt, __fadd_rn(-outA.z, fUA.z)));
        hA.w = __fadd_rn(hA.w, __fmul_rn(ddt, __fadd_rn(-outA.w, fUA.w)));
        hB.x = __fadd_rn(hB.x, __fmul_rn(ddt, __fadd_rn(-outB.x, fUB.x)));
        hB.y = __fadd_rn(hB.y, __fmul_rn(ddt, __fadd_rn(-outB.y, fUB.y)));
        hB.z = __fadd_rn(hB.z, __fmul_rn(ddt, __fadd_rn(-outB.z, fUB.z)));
        hB.w = __fadd_rn(hB.w, __fmul_rn(ddt, __fadd_rn(-outB.w, fUB.w)));
        p ^= 1;
    };

    for (int s = 0; s < steps; ++s) {
        double R = (double)(steps - 1 - s);
        float wx1 = (float)(TH * (1.0 - 0.5 * TH + R));
        float wx2 = (float)((1.0 - 2.0 * TH) * (0.5 + R));
        float wx3 = (float)(TH * (0.5 * TH + R));
        evalstep(d1dtF, wv1, wx1);
        evalstep(d2dtF, wv2, wx2);
        evalstep(d1dtF, wv1, wx3);
    }

    // ---- epilogue: Gv=Sv@W, Gx=Sx@W; pass x (32r x 32c warp, 8r x 4c thread) ----
    __syncthreads();                      // all eval reads of kbuf done
    float* stv = kbuf;                    // [64 k][WUS rows]
    float* stx = kbuf + 4352;
    *(float2*)(stv + (tcol + 0) * WUS + trow) = make_float2(SvA.x, SvB.x);
    *(float2*)(stv + (tcol + 1) * WUS + trow) = make_float2(SvA.y, SvB.y);
    *(float2*)(stv + (tcol + 2) * WUS + trow) = make_float2(SvA.z, SvB.z);
    *(float2*)(stv + (tcol + 3) * WUS + trow) = make_float2(SvA.w, SvB.w);
    *(float2*)(stx + (tcol + 0) * WUS + trow) = make_float2(SxA.x, SxB.x);
    *(float2*)(stx + (tcol + 1) * WUS + trow) = make_float2(SxA.y, SxB.y);
    *(float2*)(stx + (tcol + 2) * WUS + trow) = make_float2(SxA.z, SxB.z);
    *(float2*)(stx + (tcol + 3) * WUS + trow) = make_float2(SxA.w, SxB.w);

    const float dtF      = 0.01f;
    const float dt2F     = 1e-4f;
    const float stepsF   = (float)steps;
    const float stepsdtF = (float)((double)steps * 0.01);
    const float GamF     = (float)Gam;

    const int epass = wid >> 3;           // 0 = v-pass, 1 = x-pass
    const int rb    = (wid >> 2) & 1;
    const int cb    = wid & 3;
    const int r0e   = rb * 32 + (lane >> 3) * 8;   // 8 rows r0e..r0e+7
    const int cloc  = cb * 32 + (lane & 7) * 4;    // 4 cols

    #pragma unroll 1
    for (int P = 0; P < 4; ++P) {
        CP_WAIT0(); __syncthreads();      // W chunk P ready; S stores ordered (P==0)
        const float* sb = (epass ? stx : stv) + r0e;
        const float* wb = stage + cloc;
        float4 A[8];
        #pragma unroll
        for (int i = 0; i < 8; ++i) A[i] = make_float4(0.f,0.f,0.f,0.f);
        #pragma unroll 8
        for (int k = 0; k < KDIM; ++k) {
            float4 s0 = *(const float4*)(sb + k * WUS);
            float4 s1 = *(const float4*)(sb + k * WUS + 4);
            float4 w4 = *(const float4*)(wb + k * 128);
            A[0].x = fmaf(s0.x, w4.x, A[0].x); A[0].y = fmaf(s0.x, w4.y, A[0].y);
            A[0].z = fmaf(s0.x, w4.z, A[0].z); A[0].w = fmaf(s0.x, w4.w, A[0].w);
            A[1].x = fmaf(s0.y, w4.x, A[1].x); A[1].y = fmaf(s0.y, w4.y, A[1].y);
            A[1].z = fmaf(s0.y, w4.z, A[1].z); A[1].w = fmaf(s0.y, w4.w, A[1].w);
            A[2].x = fmaf(s0.z, w4.x, A[2].x); A[2].y = fmaf(s0.z, w4.y, A[2].y);
            A[2].z = fmaf(s0.z, w4.z, A[2].z); A[2].w = fmaf(s0.z, w4.w, A[2].w);
            A[3].x = fmaf(s0.w, w4.x, A[3].x); A[3].y = fmaf(s0.w, w4.y, A[3].y);
            A[3].z = fmaf(s0.w, w4.z, A[3].z); A[3].w = fmaf(s0.w, w4.w, A[3].w);
            A[4].x = fmaf(s1.x, w4.x, A[4].x); A[4].y = fmaf(s1.x, w4.y, A[4].y);
            A[4].z = fmaf(s1.x, w4.z, A[4].z); A[4].w = fmaf(s1.x, w4.w, A[4].w);
            A[5].x = fmaf(s1.y, w4.x, A[5].x); A[5].y = fmaf(s1.y, w4.y, A[5].y);
            A[5].z = fmaf(s1.y, w4.z, A[5].z); A[5].w = fmaf(s1.y, w4.w, A[5].w);
            A[6].x = fmaf(s1.z, w4.x, A[6].x); A[6].y = fmaf(s1.z, w4.y, A[6].y);
            A[6].z = fmaf(s1.z, w4.z, A[6].z); A[6].w = fmaf(s1.z, w4.w, A[6].w);
            A[7].x = fmaf(s1.w, w4.x, A[7].x); A[7].y = fmaf(s1.w, w4.y, A[7].y);
            A[7].z = fmaf(s1.w, w4.z, A[7].z); A[7].w = fmaf(s1.w, w4.w, A[7].w);
        }
        const int col = P * 128 + cloc;
        #pragma unroll
        for (int i = 0; i < 8; ++i) {
            const int r = r0e + i;
            const size_t off = (size_t)(row0 + r) * DDIM + col;
            float4 fv = *(const float4*)(gf + off);
            float4 v0 = *(const float4*)(gv + off);
            if (epass == 0) {             // v = v0 + dt*(-Gv + steps*f)
                float4 o;
                o.x = __fadd_rn(v0.x, __fmul_rn(dtF, __fadd_rn(-A[i].x, __fmul_rn(stepsF, fv.x))));
                o.y = __fadd_rn(v0.y, __fmul_rn(dtF, __fadd_rn(-A[i].y, __fmul_rn(stepsF, fv.y))));
                o.z = __fadd_rn(v0.z, __fmul_rn(dtF, __fadd_rn(-A[i].z, __fmul_rn(stepsF, fv.z))));
                o.w = __fadd_rn(v0.w, __fmul_rn(dtF, __fadd_rn(-A[i].w, __fmul_rn(stepsF, fv.w))));
                *(float4*)(gov + off) = o;
            } else {                      // x = wrap(x0 + steps*dt*v0 + dt^2*(-Gx + Gam*f))
                float4 x0 = *(const float4*)(gx + off);
                float4 o;
                o.x = __fadd_rn(fmaf(stepsdtF, v0.x, x0.x), __fmul_rn(dt2F, __fadd_rn(-A[i].x, __fmul_rn(GamF, fv.x))));
                o.y = __fadd_rn(fmaf(stepsdtF, v0.y, x0.y), __fmul_rn(dt2F, __fadd_rn(-A[i].y, __fmul_rn(GamF, fv.y))));
                o.z = __fadd_rn(fmaf(stepsdtF, v0.z, x0.z), __fmul_rn(dt2F, __fadd_rn(-A[i].z, __fmul_rn(GamF, fv.z))));
                o.w = __fadd_rn(fmaf(stepsdtF, v0.w, x0.w), __fmul_rn(dt2F, __fadd_rn(-A[i].w, __fmul_rn(GamF, fv.w))));
                if (steps != 0) {
                    o.x = wrap_torus(o.x); o.y = wrap_torus(o.y);
                    o.z = wrap_torus(o.z); o.w = wrap_torus(o.w);
                }
                *(float4*)(gox + off) = o;
            }
        }
        __syncthreads();                  // chunk fully consumed
        if (P < 3) issueW(P + 1);
    }
    CP_WAIT0();
}

extern "C" void kernel_launch(void* const* d_in, const int* in_sizes, int n_in,
                              void* d_out, int out_size)
{
    const float* x = (const float*)d_in[0];
    const float* v = (const float*)d_in[1];
    const float* f = (const float*)d_in[2];
    const float* U = (const float*)d_in[3];
    const float* W = (const float*)d_in[4];
    const int* steps = (n_in >= 6) ? (const int*)d_in[5] : nullptr;

    const int B  = in_sizes[0] / DDIM;
    const int BD = B * DDIM;
    float* ox = (float*)d_out;
    float* ov = ox + BD;

    wu_kernel<<<KDIM, KDIM>>>(W, U);

    const int smem_floats = 8704 + 4352 + 13312;   // 26368
    const int smem_bytes = smem_floats * 4;        // 105,472 B
    cudaFuncSetAttribute(fr_kernel, cudaFuncAttributeMaxDynamicSharedMemorySize, smem_bytes);
    fr_kernel<<<B / CTA_M, THREADS, smem_bytes>>>(x, v, f, U, W, steps, ox, ov);
}